// round 9
// baseline (speedup 1.0000x reference)
#include <cuda_runtime.h>
#include <cstdint>
#include <math.h>

// Problem constants (fixed by the dataset)
#define BATCH   2
#define SQ      2048
#define SKV     2048
#define DIM     1024
#define HEADS   16
#define DHEAD   64
#define INNER   1024            // HEADS * DIM_HEAD
#define MQ      (BATCH * SQ)    // 4096
#define MKV     (BATCH * SKV)   // 4096

// Scratch (no cudaMalloc allowed)
__device__ float g_q  [MQ  * INNER];          // 16 MB
__device__ float g_kv [MKV * 2 * INNER];      // 32 MB (K | V)
__device__ float g_o  [MQ  * INNER];          // 16 MB

// fp32 -> tf32 (round-to-nearest) as raw bits
__device__ __forceinline__ uint32_t tf32r(float x) {
    uint32_t r;
    asm("cvt.rna.tf32.f32 %0, %1;" : "=r"(r) : "f"(x));
    return r;
}

// warp-level tf32 MMA: D[16x8] += A[16x8] * B[8x8]  (row.col)
__device__ __forceinline__ void mma_tf32(float* d, const uint32_t* a, const uint32_t* b) {
    asm volatile(
        "mma.sync.aligned.m16n8k8.row.col.f32.tf32.tf32.f32 "
        "{%0,%1,%2,%3}, {%4,%5,%6,%7}, {%8,%9}, {%0,%1,%2,%3};"
        : "+f"(d[0]), "+f"(d[1]), "+f"(d[2]), "+f"(d[3])
        : "r"(a[0]), "r"(a[1]), "r"(a[2]), "r"(a[3]), "r"(b[0]), "r"(b[1]));
}

// ===========================================================================
// tf32 tensor-core GEMM: C[M,N] = A[M,K] @ B[K,N] (+ bias)
// 128x128 CTA tile, 512 threads (16 warps, 4x4 grid of 32x32 warp tiles),
// K-tile 32, double buffer, ONE sync per chunk. ~95 regs/thread so the
// full 512-thread CTA fits the RF -> 16 warps resident per SM.
// ===========================================================================
#define ALD 36
#define BLD 136
#define A_TILE_F (128 * ALD)
#define B_TILE_F (32 * BLD)
#define SM_FLOATS (2 * (A_TILE_F + B_TILE_F))
#define SM_BYTES  (SM_FLOATS * 4)   // 71680

__global__ __launch_bounds__(512) void gemm_tf32mma(
    const float* __restrict__ A, const float* __restrict__ B,
    float* __restrict__ C, const float* __restrict__ bias,
    int K, int lda, int ldb, int ldc)
{
    extern __shared__ float smem[];
    float* As[2] = { smem,            smem + A_TILE_F + B_TILE_F };
    float* Bs[2] = { smem + A_TILE_F, smem + 2 * A_TILE_F + B_TILE_F };

    const int tid  = threadIdx.x;
    const int wid  = tid >> 5;        // 0..15
    const int lane = tid & 31;
    const int g    = lane >> 2;
    const int t    = lane & 3;
    const int wrow = (wid & 3) * 32;  // 4 warp rows
    const int wcol = (wid >> 2) * 32; // 4 warp cols

    const int brow = blockIdx.y * 128;
    const int bcol = blockIdx.x * 128;

    float acc[2][4][4];
    #pragma unroll
    for (int i = 0; i < 2; i++)
        #pragma unroll
        for (int j = 0; j < 4; j++)
            #pragma unroll
            for (int r = 0; r < 4; r++) acc[i][j][r] = 0.f;

    const float* Ab = A + (size_t)brow * lda;
    const float* Bb = B + bcol;

    // A tile: 128x32 = 1024 float4; B tile: 32x128 = 1024 float4; 2 each/thread
    auto load_regs = [&](int k0, float4* pa, float4* pb) {
        #pragma unroll
        for (int i = 0; i < 2; i++) {
            const int idx = i * 512 + tid;
            const int ar = idx >> 3, ac4 = (idx & 7) * 4;
            pa[i] = *(const float4*)(Ab + (size_t)ar * lda + k0 + ac4);
            const int br = idx >> 5, bc4 = (idx & 31) * 4;
            pb[i] = *(const float4*)(Bb + (size_t)(k0 + br) * ldb + bc4);
        }
    };
    auto store_smem = [&](int buf, const float4* pa, const float4* pb) {
        #pragma unroll
        for (int i = 0; i < 2; i++) {
            const int idx = i * 512 + tid;
            const int ar = idx >> 3, ac4 = (idx & 7) * 4;
            uint4 ua; ua.x = tf32r(pa[i].x); ua.y = tf32r(pa[i].y);
                      ua.z = tf32r(pa[i].z); ua.w = tf32r(pa[i].w);
            *(uint4*)(As[buf] + ar * ALD + ac4) = ua;
            const int br = idx >> 5, bc4 = (idx & 31) * 4;
            uint4 ub; ub.x = tf32r(pb[i].x); ub.y = tf32r(pb[i].y);
                      ub.z = tf32r(pb[i].z); ub.w = tf32r(pb[i].w);
            *(uint4*)(Bs[buf] + br * BLD + bc4) = ub;
        }
    };

    {
        float4 pa[2], pb[2];
        load_regs(0, pa, pb);
        store_smem(0, pa, pb);
    }
    __syncthreads();

    const int nch = K >> 5;
    for (int ch = 0; ch < nch; ch++) {
        const int buf = ch & 1;

        float4 pa[2], pb[2];
        if (ch + 1 < nch) load_regs((ch + 1) * 32, pa, pb);

        const uint32_t* Asb = (const uint32_t*)As[buf];
        const uint32_t* Bsb = (const uint32_t*)Bs[buf];

        #pragma unroll
        for (int ks = 0; ks < 4; ks++) {
            const int k0 = ks * 8;
            uint32_t af[2][4], bf[4][2];
            #pragma unroll
            for (int i = 0; i < 2; i++) {
                const int r0 = wrow + i * 16 + g;
                af[i][0] = Asb[(r0    ) * ALD + k0 + t];
                af[i][1] = Asb[(r0 + 8) * ALD + k0 + t];
                af[i][2] = Asb[(r0    ) * ALD + k0 + t + 4];
                af[i][3] = Asb[(r0 + 8) * ALD + k0 + t + 4];
            }
            #pragma unroll
            for (int j = 0; j < 4; j++) {
                const int c = wcol + j * 8 + g;
                bf[j][0] = Bsb[(k0 + t    ) * BLD + c];
                bf[j][1] = Bsb[(k0 + t + 4) * BLD + c];
            }
            #pragma unroll
            for (int i = 0; i < 2; i++)
                #pragma unroll
                for (int j = 0; j < 4; j++)
                    mma_tf32(acc[i][j], af[i], bf[j]);
        }

        // buf^1 was last read before the previous barrier -> safe to overwrite;
        // single barrier publishes it for the next iteration.
        if (ch + 1 < nch) store_smem(buf ^ 1, pa, pb);
        __syncthreads();
    }

    #pragma unroll
    for (int i = 0; i < 2; i++) {
        const int r0 = brow + wrow + i * 16 + g;
        #pragma unroll
        for (int j = 0; j < 4; j++) {
            const int c = bcol + wcol + j * 8 + 2 * t;
            float b0 = 0.f, b1 = 0.f;
            if (bias) { b0 = bias[c]; b1 = bias[c + 1]; }
            float2 v0 = { acc[i][j][0] + b0, acc[i][j][1] + b1 };
            float2 v1 = { acc[i][j][2] + b0, acc[i][j][3] + b1 };
            *(float2*)(C + (size_t)r0 * ldc + c)       = v0;
            *(float2*)(C + (size_t)(r0 + 8) * ldc + c) = v1;
        }
    }
}

// ===========================================================================
// Tensor-core flash attention v2 (tf32 mma.sync).  UNCHANGED (round-8 WIN)
// CTA: 256 q-rows x (b,h), 512 threads = 16 warps x 16 rows.
// KV tiles of 32 rows, double-buffered smem + register prefetch,
// ONE __syncthreads per tile. Warp-uniform running max.
// ===========================================================================
#define KT    32
#define KPAD  68
#define VPAD  72
#define PPAD  36
#define KS_F  (KT * KPAD)
#define VS_F  (KT * VPAD)
#define BUF_F (KS_F + VS_F)
#define PS_F  (16 * 16 * PPAD)
#define ATT_SM_F     (2 * BUF_F + PS_F)
#define ATT_SM_BYTES (ATT_SM_F * 4) // 72704

__global__ __launch_bounds__(512) void attn_tc(
    const float* __restrict__ Q, const float* __restrict__ KV,
    float* __restrict__ O)
{
    extern __shared__ float asm_[];
    uint32_t* Pb = (uint32_t*)(asm_ + 2 * BUF_F);

    const int tid  = threadIdx.x;
    const int wid  = tid >> 5;
    const int lane = tid & 31;
    const int g    = lane >> 2;
    const int t    = lane & 3;

    const int qt = blockIdx.x;
    const int h  = blockIdx.y;
    const int b  = blockIdx.z;

    const int qrow0  = qt * 256 + wid * 16 + g;
    const size_t qg0 = ((size_t)b * SQ + qrow0) * INNER + h * DHEAD;

    uint32_t qa[8][4];
    {
        const float* q0 = Q + qg0;
        const float* q1 = q0 + 8 * INNER;
        #pragma unroll
        for (int ks = 0; ks < 8; ks++) {
            qa[ks][0] = tf32r(0.125f * q0[8 * ks + t]);
            qa[ks][1] = tf32r(0.125f * q1[8 * ks + t]);
            qa[ks][2] = tf32r(0.125f * q0[8 * ks + t + 4]);
            qa[ks][3] = tf32r(0.125f * q1[8 * ks + t + 4]);
        }
    }

    float m = -INFINITY;
    float l0 = 0.f, l1 = 0.f;
    float o[8][4];
    #pragma unroll
    for (int j = 0; j < 8; j++)
        #pragma unroll
        for (int r = 0; r < 4; r++) o[j][r] = 0.f;

    const int pbase = wid * 16 * PPAD;

    const int ldj  = tid >> 4;
    const int ldd4 = (tid & 15) * 4;
    auto ldtile = [&](int n, float4& kr, float4& vr) {
        const float* p = KV + ((size_t)b * SKV + n * KT + ldj) * (2 * INNER)
                            + h * DHEAD + ldd4;
        kr = *(const float4*)p;
        vr = *(const float4*)(p + INNER);
    };
    auto sttile = [&](int buf, const float4& kr, const float4& vr) {
        uint32_t* kb = (uint32_t*)(asm_ + buf * BUF_F);
        uint32_t* vb = kb + KS_F;
        uint4 uk; uk.x = tf32r(kr.x); uk.y = tf32r(kr.y);
                  uk.z = tf32r(kr.z); uk.w = tf32r(kr.w);
        *(uint4*)(kb + ldj * KPAD + ldd4) = uk;
        uint4 uv; uv.x = tf32r(vr.x); uv.y = tf32r(vr.y);
                  uv.z = tf32r(vr.z); uv.w = tf32r(vr.w);
        *(uint4*)(vb + ldj * VPAD + ldd4) = uv;
    };

    {
        float4 kr, vr;
        ldtile(0, kr, vr);
        sttile(0, kr, vr);
    }
    __syncthreads();

    const int NT = SKV / KT;
    for (int n = 0; n < NT; n++) {
        const int buf = n & 1;

        float4 krn, vrn;
        if (n + 1 < NT) ldtile(n + 1, krn, vrn);

        const uint32_t* Ksb = (const uint32_t*)(asm_ + buf * BUF_F);
        const uint32_t* Vsb = Ksb + KS_F;

        float s[4][4];
        #pragma unroll
        for (int j = 0; j < 4; j++)
            #pragma unroll
            for (int r = 0; r < 4; r++) s[j][r] = 0.f;

        #pragma unroll
        for (int ks = 0; ks < 8; ks++) {
            const int k0 = ks * 8;
            uint32_t bf[4][2];
            #pragma unroll
            for (int j = 0; j < 4; j++) {
                const int nn = j * 8 + g;
                bf[j][0] = Ksb[nn * KPAD + k0 + t];
                bf[j][1] = Ksb[nn * KPAD + k0 + t + 4];
            }
            #pragma unroll
            for (int j = 0; j < 4; j++)
                mma_tf32(s[j], qa[ks], bf[j]);
        }

        float tm = -INFINITY;
        #pragma unroll
        for (int j = 0; j < 4; j++) {
            tm = fmaxf(tm, fmaxf(fmaxf(s[j][0], s[j][1]),
                                 fmaxf(s[j][2], s[j][3])));
        }
        #pragma unroll
        for (int d = 16; d >= 1; d >>= 1)
            tm = fmaxf(tm, __shfl_xor_sync(0xffffffffu, tm, d));

        const float mn = fmaxf(m, tm);
        const float a  = __expf(m - mn);
        if (a < 1.f) {
            l0 *= a; l1 *= a;
            #pragma unroll
            for (int j = 0; j < 8; j++) {
                o[j][0] *= a; o[j][1] *= a; o[j][2] *= a; o[j][3] *= a;
            }
        }
        m = mn;

        float rs0 = 0.f, rs1 = 0.f;
        #pragma unroll
        for (int j = 0; j < 4; j++) {
            const float p0 = __expf(s[j][0] - m);
            const float p1 = __expf(s[j][1] - m);
            const float p2 = __expf(s[j][2] - m);
            const float p3 = __expf(s[j][3] - m);
            rs0 += p0 + p1;
            rs1 += p2 + p3;
            const int c = j * 8 + 2 * t;
            Pb[pbase + g * PPAD + c]           = tf32r(p0);
            Pb[pbase + g * PPAD + c + 1]       = tf32r(p1);
            Pb[pbase + (g + 8) * PPAD + c]     = tf32r(p2);
            Pb[pbase + (g + 8) * PPAD + c + 1] = tf32r(p3);
        }
        rs0 += __shfl_xor_sync(0xffffffffu, rs0, 1);
        rs0 += __shfl_xor_sync(0xffffffffu, rs0, 2);
        rs1 += __shfl_xor_sync(0xffffffffu, rs1, 1);
        rs1 += __shfl_xor_sync(0xffffffffu, rs1, 2);
        l0 += rs0; l1 += rs1;

        __syncwarp();

        #pragma unroll
        for (int ks = 0; ks < 4; ks++) {
            const int k0 = ks * 8;
            uint32_t pa[4];
            pa[0] = Pb[pbase + g * PPAD + k0 + t];
            pa[1] = Pb[pbase + (g + 8) * PPAD + k0 + t];
            pa[2] = Pb[pbase + g * PPAD + k0 + t + 4];
            pa[3] = Pb[pbase + (g + 8) * PPAD + k0 + t + 4];
            #pragma unroll
            for (int j = 0; j < 8; j++) {
                uint32_t bf[2];
                const int nn = j * 8 + g;
                bf[0] = Vsb[(k0 + t    ) * VPAD + nn];
                bf[1] = Vsb[(k0 + t + 4) * VPAD + nn];
                mma_tf32(o[j], pa, bf);
            }
        }
        __syncwarp();

        if (n + 1 < NT) sttile(buf ^ 1, krn, vrn);
        __syncthreads();
    }

    const float inv0 = 1.f / l0;
    const float inv1 = 1.f / l1;
    float* o0 = O + qg0;
    float* o1 = o0 + 8 * INNER;
    #pragma unroll
    for (int j = 0; j < 8; j++) {
        const int c = j * 8 + 2 * t;
        float2 v0 = { o[j][0] * inv0, o[j][1] * inv0 };
        float2 v1 = { o[j][2] * inv1, o[j][3] * inv1 };
        *(float2*)(o0 + c) = v0;
        *(float2*)(o1 + c) = v1;
    }
}

// ===========================================================================
// kernel_launch
// ===========================================================================
extern "C" void kernel_launch(void* const* d_in, const int* in_sizes, int n_in,
                              void* d_out, int out_size)
{
    const float* x_q   = (const float*)d_in[0];
    const float* x_kv  = (const float*)d_in[1];
    const float* W_qkv = (const float*)d_in[2];  // [1024, 3072]
    const float* W_out = (const float*)d_in[3];  // [1024, 1024]
    const float* b_out = (const float*)d_in[4];  // [1024]
    float* out = (float*)d_out;

    float *q, *kv, *o;
    cudaGetSymbolAddress((void**)&q,  g_q);
    cudaGetSymbolAddress((void**)&kv, g_kv);
    cudaGetSymbolAddress((void**)&o,  g_o);

    cudaFuncSetAttribute(gemm_tf32mma,
                         cudaFuncAttributeMaxDynamicSharedMemorySize, SM_BYTES);
    cudaFuncSetAttribute(attn_tc,
                         cudaFuncAttributeMaxDynamicSharedMemorySize, ATT_SM_BYTES);

    // Q = x_q @ W_qkv[:, 0:1024]             -> [4096, 1024]
    gemm_tf32mma<<<dim3(INNER / 128, MQ / 128), 512, SM_BYTES>>>(
        x_q, W_qkv, q, nullptr, DIM, DIM, 3 * INNER, INNER);

    // KV = x_kv @ W_qkv[:, 1024:3072]        -> [4096, 2048]  (K | V)
    gemm_tf32mma<<<dim3(2 * INNER / 128, MKV / 128), 512, SM_BYTES>>>(
        x_kv, W_qkv + INNER, kv, nullptr, DIM, DIM, 3 * INNER, 2 * INNER);

    // attention (tensor core, fa2)            -> O [4096, 1024]
    attn_tc<<<dim3(SQ / 256, HEADS, BATCH), 512, ATT_SM_BYTES>>>(q, kv, o);

    // out = O @ W_out + b_out                 -> [4096, 1024]
    gemm_tf32mma<<<dim3(DIM / 128, MQ / 128), 512, SM_BYTES>>>(
        o, W_out, out, b_out, INNER, INNER, INNER, DIM);
}

// round 10
// speedup vs baseline: 1.1095x; 1.1095x over previous
#include <cuda_runtime.h>
#include <cstdint>
#include <math.h>

// Problem constants (fixed by the dataset)
#define BATCH   2
#define SQ      2048
#define SKV     2048
#define DIM     1024
#define HEADS   16
#define DHEAD   64
#define INNER   1024            // HEADS * DIM_HEAD
#define MQ      (BATCH * SQ)    // 4096
#define MKV     (BATCH * SKV)   // 4096

// Scratch (no cudaMalloc allowed)
__device__ float g_q  [MQ  * INNER];          // 16 MB
__device__ float g_kv [MKV * 2 * INNER];      // 32 MB (K | V)
__device__ float g_o  [MQ  * INNER];          // 16 MB

// fp32 -> tf32 (round-to-nearest) as raw bits
__device__ __forceinline__ uint32_t tf32r(float x) {
    uint32_t r;
    asm("cvt.rna.tf32.f32 %0, %1;" : "=r"(r) : "f"(x));
    return r;
}

// warp-level tf32 MMA: D[16x8] += A[16x8] * B[8x8]  (row.col)
__device__ __forceinline__ void mma_tf32(float* d, const uint32_t* a, const uint32_t* b) {
    asm volatile(
        "mma.sync.aligned.m16n8k8.row.col.f32.tf32.tf32.f32 "
        "{%0,%1,%2,%3}, {%4,%5,%6,%7}, {%8,%9}, {%0,%1,%2,%3};"
        : "+f"(d[0]), "+f"(d[1]), "+f"(d[2]), "+f"(d[3])
        : "r"(a[0]), "r"(a[1]), "r"(a[2]), "r"(a[3]), "r"(b[0]), "r"(b[1]));
}

// ===========================================================================
// tf32 tensor-core GEMM: C[M,N] = A[M,K] @ B[K,N] (+ bias)
// CTA tile 128x64, 256 threads (8 warps, 4x2 grid of 32x32 warp tiles),
// K-tile 32, double buffer, ONE sync per chunk.
// __launch_bounds__(256, 2): TWO independent CTAs per SM so the per-chunk
// __syncthreads of one CTA no longer stalls the whole SM (barrier decoupling).
// ===========================================================================
#define ALD 36                   // A smem pitch: frag banks 4g+t, conflict-free
#define BLD 72                   // B smem pitch (72 % 32 == 8): frag banks 8t+g
#define A_TILE_F (128 * ALD)     // 4608
#define B_TILE_F (32 * BLD)      // 2304
#define SM_FLOATS (2 * (A_TILE_F + B_TILE_F))
#define SM_BYTES  (SM_FLOATS * 4)   // 55296

__global__ __launch_bounds__(256, 2) void gemm_tf32mma(
    const float* __restrict__ A, const float* __restrict__ B,
    float* __restrict__ C, const float* __restrict__ bias,
    int K, int lda, int ldb, int ldc)
{
    extern __shared__ float smem[];
    float* As[2] = { smem,            smem + A_TILE_F + B_TILE_F };
    float* Bs[2] = { smem + A_TILE_F, smem + 2 * A_TILE_F + B_TILE_F };

    const int tid  = threadIdx.x;
    const int wid  = tid >> 5;        // 0..7
    const int lane = tid & 31;
    const int g    = lane >> 2;
    const int t    = lane & 3;
    const int wrow = (wid & 3) * 32;  // 4 warp rows
    const int wcol = (wid >> 2) * 32; // 2 warp cols

    const int brow = blockIdx.y * 128;
    const int bcol = blockIdx.x * 64;

    float acc[2][4][4];
    #pragma unroll
    for (int i = 0; i < 2; i++)
        #pragma unroll
        for (int j = 0; j < 4; j++)
            #pragma unroll
            for (int r = 0; r < 4; r++) acc[i][j][r] = 0.f;

    const float* Ab = A + (size_t)brow * lda;
    const float* Bb = B + bcol;

    // A tile: 128x32 = 1024 float4 -> 4/thread; B tile: 32x64 = 512 float4 -> 2/thread
    auto load_regs = [&](int k0, float4* pa, float4* pb) {
        #pragma unroll
        for (int i = 0; i < 4; i++) {
            const int idx = i * 256 + tid;
            const int ar = idx >> 3, ac4 = (idx & 7) * 4;
            pa[i] = *(const float4*)(Ab + (size_t)ar * lda + k0 + ac4);
        }
        #pragma unroll
        for (int i = 0; i < 2; i++) {
            const int idx = i * 256 + tid;
            const int br = idx >> 4, bc4 = (idx & 15) * 4;
            pb[i] = *(const float4*)(Bb + (size_t)(k0 + br) * ldb + bc4);
        }
    };
    auto store_smem = [&](int buf, const float4* pa, const float4* pb) {
        #pragma unroll
        for (int i = 0; i < 4; i++) {
            const int idx = i * 256 + tid;
            const int ar = idx >> 3, ac4 = (idx & 7) * 4;
            uint4 ua; ua.x = tf32r(pa[i].x); ua.y = tf32r(pa[i].y);
                      ua.z = tf32r(pa[i].z); ua.w = tf32r(pa[i].w);
            *(uint4*)(As[buf] + ar * ALD + ac4) = ua;
        }
        #pragma unroll
        for (int i = 0; i < 2; i++) {
            const int idx = i * 256 + tid;
            const int br = idx >> 4, bc4 = (idx & 15) * 4;
            uint4 ub; ub.x = tf32r(pb[i].x); ub.y = tf32r(pb[i].y);
                      ub.z = tf32r(pb[i].z); ub.w = tf32r(pb[i].w);
            *(uint4*)(Bs[buf] + br * BLD + bc4) = ub;
        }
    };

    {
        float4 pa[4], pb[2];
        load_regs(0, pa, pb);
        store_smem(0, pa, pb);
    }
    __syncthreads();

    const int nch = K >> 5;
    for (int ch = 0; ch < nch; ch++) {
        const int buf = ch & 1;

        float4 pa[4], pb[2];
        if (ch + 1 < nch) load_regs((ch + 1) * 32, pa, pb);

        const uint32_t* Asb = (const uint32_t*)As[buf];
        const uint32_t* Bsb = (const uint32_t*)Bs[buf];

        #pragma unroll
        for (int ks = 0; ks < 4; ks++) {
            const int k0 = ks * 8;
            uint32_t af[2][4], bf[4][2];
            #pragma unroll
            for (int i = 0; i < 2; i++) {
                const int r0 = wrow + i * 16 + g;
                af[i][0] = Asb[(r0    ) * ALD + k0 + t];
                af[i][1] = Asb[(r0 + 8) * ALD + k0 + t];
                af[i][2] = Asb[(r0    ) * ALD + k0 + t + 4];
                af[i][3] = Asb[(r0 + 8) * ALD + k0 + t + 4];
            }
            #pragma unroll
            for (int j = 0; j < 4; j++) {
                const int c = wcol + j * 8 + g;
                bf[j][0] = Bsb[(k0 + t    ) * BLD + c];
                bf[j][1] = Bsb[(k0 + t + 4) * BLD + c];
            }
            #pragma unroll
            for (int i = 0; i < 2; i++)
                #pragma unroll
                for (int j = 0; j < 4; j++)
                    mma_tf32(acc[i][j], af[i], bf[j]);
        }

        // buf^1 was last read before the previous barrier -> safe to overwrite;
        // single barrier publishes it for the next iteration.
        if (ch + 1 < nch) store_smem(buf ^ 1, pa, pb);
        __syncthreads();
    }

    #pragma unroll
    for (int i = 0; i < 2; i++) {
        const int r0 = brow + wrow + i * 16 + g;
        #pragma unroll
        for (int j = 0; j < 4; j++) {
            const int c = bcol + wcol + j * 8 + 2 * t;
            float b0 = 0.f, b1 = 0.f;
            if (bias) { b0 = bias[c]; b1 = bias[c + 1]; }
            float2 v0 = { acc[i][j][0] + b0, acc[i][j][1] + b1 };
            float2 v1 = { acc[i][j][2] + b0, acc[i][j][3] + b1 };
            *(float2*)(C + (size_t)r0 * ldc + c)       = v0;
            *(float2*)(C + (size_t)(r0 + 8) * ldc + c) = v1;
        }
    }
}

// ===========================================================================
// Tensor-core flash attention v2 (tf32 mma.sync).  UNCHANGED (round-8 WIN)
// CTA: 256 q-rows x (b,h), 512 threads = 16 warps x 16 rows.
// KV tiles of 32 rows, double-buffered smem + register prefetch,
// ONE __syncthreads per tile. Warp-uniform running max.
// ===========================================================================
#define KT    32
#define KPAD  68
#define VPAD  72
#define PPAD  36
#define KS_F  (KT * KPAD)
#define VS_F  (KT * VPAD)
#define BUF_F (KS_F + VS_F)
#define PS_F  (16 * 16 * PPAD)
#define ATT_SM_F     (2 * BUF_F + PS_F)
#define ATT_SM_BYTES (ATT_SM_F * 4) // 72704

__global__ __launch_bounds__(512) void attn_tc(
    const float* __restrict__ Q, const float* __restrict__ KV,
    float* __restrict__ O)
{
    extern __shared__ float asm_[];
    uint32_t* Pb = (uint32_t*)(asm_ + 2 * BUF_F);

    const int tid  = threadIdx.x;
    const int wid  = tid >> 5;
    const int lane = tid & 31;
    const int g    = lane >> 2;
    const int t    = lane & 3;

    const int qt = blockIdx.x;
    const int h  = blockIdx.y;
    const int b  = blockIdx.z;

    const int qrow0  = qt * 256 + wid * 16 + g;
    const size_t qg0 = ((size_t)b * SQ + qrow0) * INNER + h * DHEAD;

    uint32_t qa[8][4];
    {
        const float* q0 = Q + qg0;
        const float* q1 = q0 + 8 * INNER;
        #pragma unroll
        for (int ks = 0; ks < 8; ks++) {
            qa[ks][0] = tf32r(0.125f * q0[8 * ks + t]);
            qa[ks][1] = tf32r(0.125f * q1[8 * ks + t]);
            qa[ks][2] = tf32r(0.125f * q0[8 * ks + t + 4]);
            qa[ks][3] = tf32r(0.125f * q1[8 * ks + t + 4]);
        }
    }

    float m = -INFINITY;
    float l0 = 0.f, l1 = 0.f;
    float o[8][4];
    #pragma unroll
    for (int j = 0; j < 8; j++)
        #pragma unroll
        for (int r = 0; r < 4; r++) o[j][r] = 0.f;

    const int pbase = wid * 16 * PPAD;

    const int ldj  = tid >> 4;
    const int ldd4 = (tid & 15) * 4;
    auto ldtile = [&](int n, float4& kr, float4& vr) {
        const float* p = KV + ((size_t)b * SKV + n * KT + ldj) * (2 * INNER)
                            + h * DHEAD + ldd4;
        kr = *(const float4*)p;
        vr = *(const float4*)(p + INNER);
    };
    auto sttile = [&](int buf, const float4& kr, const float4& vr) {
        uint32_t* kb = (uint32_t*)(asm_ + buf * BUF_F);
        uint32_t* vb = kb + KS_F;
        uint4 uk; uk.x = tf32r(kr.x); uk.y = tf32r(kr.y);
                  uk.z = tf32r(kr.z); uk.w = tf32r(kr.w);
        *(uint4*)(kb + ldj * KPAD + ldd4) = uk;
        uint4 uv; uv.x = tf32r(vr.x); uv.y = tf32r(vr.y);
                  uv.z = tf32r(vr.z); uv.w = tf32r(vr.w);
        *(uint4*)(vb + ldj * VPAD + ldd4) = uv;
    };

    {
        float4 kr, vr;
        ldtile(0, kr, vr);
        sttile(0, kr, vr);
    }
    __syncthreads();

    const int NT = SKV / KT;
    for (int n = 0; n < NT; n++) {
        const int buf = n & 1;

        float4 krn, vrn;
        if (n + 1 < NT) ldtile(n + 1, krn, vrn);

        const uint32_t* Ksb = (const uint32_t*)(asm_ + buf * BUF_F);
        const uint32_t* Vsb = Ksb + KS_F;

        float s[4][4];
        #pragma unroll
        for (int j = 0; j < 4; j++)
            #pragma unroll
            for (int r = 0; r < 4; r++) s[j][r] = 0.f;

        #pragma unroll
        for (int ks = 0; ks < 8; ks++) {
            const int k0 = ks * 8;
            uint32_t bf[4][2];
            #pragma unroll
            for (int j = 0; j < 4; j++) {
                const int nn = j * 8 + g;
                bf[j][0] = Ksb[nn * KPAD + k0 + t];
                bf[j][1] = Ksb[nn * KPAD + k0 + t + 4];
            }
            #pragma unroll
            for (int j = 0; j < 4; j++)
                mma_tf32(s[j], qa[ks], bf[j]);
        }

        float tm = -INFINITY;
        #pragma unroll
        for (int j = 0; j < 4; j++) {
            tm = fmaxf(tm, fmaxf(fmaxf(s[j][0], s[j][1]),
                                 fmaxf(s[j][2], s[j][3])));
        }
        #pragma unroll
        for (int d = 16; d >= 1; d >>= 1)
            tm = fmaxf(tm, __shfl_xor_sync(0xffffffffu, tm, d));

        const float mn = fmaxf(m, tm);
        const float a  = __expf(m - mn);
        if (a < 1.f) {
            l0 *= a; l1 *= a;
            #pragma unroll
            for (int j = 0; j < 8; j++) {
                o[j][0] *= a; o[j][1] *= a; o[j][2] *= a; o[j][3] *= a;
            }
        }
        m = mn;

        float rs0 = 0.f, rs1 = 0.f;
        #pragma unroll
        for (int j = 0; j < 4; j++) {
            const float p0 = __expf(s[j][0] - m);
            const float p1 = __expf(s[j][1] - m);
            const float p2 = __expf(s[j][2] - m);
            const float p3 = __expf(s[j][3] - m);
            rs0 += p0 + p1;
            rs1 += p2 + p3;
            const int c = j * 8 + 2 * t;
            Pb[pbase + g * PPAD + c]           = tf32r(p0);
            Pb[pbase + g * PPAD + c + 1]       = tf32r(p1);
            Pb[pbase + (g + 8) * PPAD + c]     = tf32r(p2);
            Pb[pbase + (g + 8) * PPAD + c + 1] = tf32r(p3);
        }
        rs0 += __shfl_xor_sync(0xffffffffu, rs0, 1);
        rs0 += __shfl_xor_sync(0xffffffffu, rs0, 2);
        rs1 += __shfl_xor_sync(0xffffffffu, rs1, 1);
        rs1 += __shfl_xor_sync(0xffffffffu, rs1, 2);
        l0 += rs0; l1 += rs1;

        __syncwarp();

        #pragma unroll
        for (int ks = 0; ks < 4; ks++) {
            const int k0 = ks * 8;
            uint32_t pa[4];
            pa[0] = Pb[pbase + g * PPAD + k0 + t];
            pa[1] = Pb[pbase + (g + 8) * PPAD + k0 + t];
            pa[2] = Pb[pbase + g * PPAD + k0 + t + 4];
            pa[3] = Pb[pbase + (g + 8) * PPAD + k0 + t + 4];
            #pragma unroll
            for (int j = 0; j < 8; j++) {
                uint32_t bf[2];
                const int nn = j * 8 + g;
                bf[0] = Vsb[(k0 + t    ) * VPAD + nn];
                bf[1] = Vsb[(k0 + t + 4) * VPAD + nn];
                mma_tf32(o[j], pa, bf);
            }
        }
        __syncwarp();

        if (n + 1 < NT) sttile(buf ^ 1, krn, vrn);
        __syncthreads();
    }

    const float inv0 = 1.f / l0;
    const float inv1 = 1.f / l1;
    float* o0 = O + qg0;
    float* o1 = o0 + 8 * INNER;
    #pragma unroll
    for (int j = 0; j < 8; j++) {
        const int c = j * 8 + 2 * t;
        float2 v0 = { o[j][0] * inv0, o[j][1] * inv0 };
        float2 v1 = { o[j][2] * inv1, o[j][3] * inv1 };
        *(float2*)(o0 + c) = v0;
        *(float2*)(o1 + c) = v1;
    }
}

// ===========================================================================
// kernel_launch
// ===========================================================================
extern "C" void kernel_launch(void* const* d_in, const int* in_sizes, int n_in,
                              void* d_out, int out_size)
{
    const float* x_q   = (const float*)d_in[0];
    const float* x_kv  = (const float*)d_in[1];
    const float* W_qkv = (const float*)d_in[2];  // [1024, 3072]
    const float* W_out = (const float*)d_in[3];  // [1024, 1024]
    const float* b_out = (const float*)d_in[4];  // [1024]
    float* out = (float*)d_out;

    float *q, *kv, *o;
    cudaGetSymbolAddress((void**)&q,  g_q);
    cudaGetSymbolAddress((void**)&kv, g_kv);
    cudaGetSymbolAddress((void**)&o,  g_o);

    cudaFuncSetAttribute(gemm_tf32mma,
                         cudaFuncAttributeMaxDynamicSharedMemorySize, SM_BYTES);
    cudaFuncSetAttribute(attn_tc,
                         cudaFuncAttributeMaxDynamicSharedMemorySize, ATT_SM_BYTES);

    // Q = x_q @ W_qkv[:, 0:1024]             -> [4096, 1024]
    gemm_tf32mma<<<dim3(INNER / 64, MQ / 128), 256, SM_BYTES>>>(
        x_q, W_qkv, q, nullptr, DIM, DIM, 3 * INNER, INNER);

    // KV = x_kv @ W_qkv[:, 1024:3072]        -> [4096, 2048]  (K | V)
    gemm_tf32mma<<<dim3(2 * INNER / 64, MKV / 128), 256, SM_BYTES>>>(
        x_kv, W_qkv + INNER, kv, nullptr, DIM, DIM, 3 * INNER, 2 * INNER);

    // attention (tensor core, fa2)            -> O [4096, 1024]
    attn_tc<<<dim3(SQ / 256, HEADS, BATCH), 512, ATT_SM_BYTES>>>(q, kv, o);

    // out = O @ W_out + b_out                 -> [4096, 1024]
    gemm_tf32mma<<<dim3(DIM / 64, MQ / 128), 256, SM_BYTES>>>(
        o, W_out, out, b_out, INNER, INNER, INNER, DIM);
}

// round 11
// speedup vs baseline: 1.1385x; 1.0262x over previous
#include <cuda_runtime.h>
#include <cstdint>
#include <math.h>

// Problem constants (fixed by the dataset)
#define BATCH   2
#define SQ      2048
#define SKV     2048
#define DIM     1024
#define HEADS   16
#define DHEAD   64
#define INNER   1024            // HEADS * DIM_HEAD
#define MQ      (BATCH * SQ)    // 4096
#define MKV     (BATCH * SKV)   // 4096

// Scratch (no cudaMalloc allowed)
__device__ float g_q  [MQ  * INNER];          // 16 MB
__device__ float g_kv [MKV * 2 * INNER];      // 32 MB (K | V)
__device__ float g_o  [MQ  * INNER];          // 16 MB

// fp32 -> tf32 (round-to-nearest) as raw bits
__device__ __forceinline__ uint32_t tf32r(float x) {
    uint32_t r;
    asm("cvt.rna.tf32.f32 %0, %1;" : "=r"(r) : "f"(x));
    return r;
}

// warp-level tf32 MMA: D[16x8] += A[16x8] * B[8x8]  (row.col)
__device__ __forceinline__ void mma_tf32(float* d, const uint32_t* a, const uint32_t* b) {
    asm volatile(
        "mma.sync.aligned.m16n8k8.row.col.f32.tf32.tf32.f32 "
        "{%0,%1,%2,%3}, {%4,%5,%6,%7}, {%8,%9}, {%0,%1,%2,%3};"
        : "+f"(d[0]), "+f"(d[1]), "+f"(d[2]), "+f"(d[3])
        : "r"(a[0]), "r"(a[1]), "r"(a[2]), "r"(a[3]), "r"(b[0]), "r"(b[1]));
}

// async 16B copy gmem -> smem (Ampere+ LDGSTS; family-wide, OK on sm_103)
__device__ __forceinline__ void cp_async16(void* sptr, const void* gptr) {
    uint32_t sa = (uint32_t)__cvta_generic_to_shared(sptr);
    asm volatile("cp.async.cg.shared.global [%0], [%1], 16;" :: "r"(sa), "l"(gptr));
}
#define CP_COMMIT()  asm volatile("cp.async.commit_group;" ::: "memory")
#define CP_WAIT0()   asm volatile("cp.async.wait_group 0;" ::: "memory")

// ===========================================================================
// tf32 tensor-core GEMM: C[M,N] = A[M,K] @ B[K,N] (+ bias)
// CTA tile 128x64, 256 threads (8 warps, 4x2 grid of 32x32 warp tiles),
// K-tile 32, double buffer via cp.async (no reg staging, no STS pass),
// tf32 rounding applied after fragment LDS. ONE sync per chunk.
// __launch_bounds__(256, 2): two independent CTAs per SM (barrier decoupling).
// ===========================================================================
#define ALD 36                   // A smem pitch (raw fp32): frag banks 4g+t
#define BLD 72                   // B smem pitch (72 % 32 == 8): frag banks 8t+g
#define A_TILE_F (128 * ALD)     // 4608
#define B_TILE_F (32 * BLD)      // 2304
#define SM_FLOATS (2 * (A_TILE_F + B_TILE_F))
#define SM_BYTES  (SM_FLOATS * 4)   // 55296

__global__ __launch_bounds__(256, 2) void gemm_tf32mma(
    const float* __restrict__ A, const float* __restrict__ B,
    float* __restrict__ C, const float* __restrict__ bias,
    int K, int lda, int ldb, int ldc)
{
    extern __shared__ float smem[];
    float* As[2] = { smem,            smem + A_TILE_F + B_TILE_F };
    float* Bs[2] = { smem + A_TILE_F, smem + 2 * A_TILE_F + B_TILE_F };

    const int tid  = threadIdx.x;
    const int wid  = tid >> 5;        // 0..7
    const int lane = tid & 31;
    const int g    = lane >> 2;
    const int t    = lane & 3;
    const int wrow = (wid & 3) * 32;  // 4 warp rows
    const int wcol = (wid >> 2) * 32; // 2 warp cols

    const int brow = blockIdx.y * 128;
    const int bcol = blockIdx.x * 64;

    float acc[2][4][4];
    #pragma unroll
    for (int i = 0; i < 2; i++)
        #pragma unroll
        for (int j = 0; j < 4; j++)
            #pragma unroll
            for (int r = 0; r < 4; r++) acc[i][j][r] = 0.f;

    const float* Ab = A + (size_t)brow * lda;
    const float* Bb = B + bcol;

    // A tile: 128x32 = 1024 float4 -> 4 cp/thread; B tile: 32x64 = 512 -> 2 cp/thread
    auto cp_tile = [&](int k0, int buf) {
        #pragma unroll
        for (int i = 0; i < 4; i++) {
            const int idx = i * 256 + tid;
            const int ar = idx >> 3, ac4 = (idx & 7) * 4;
            cp_async16(As[buf] + ar * ALD + ac4, Ab + (size_t)ar * lda + k0 + ac4);
        }
        #pragma unroll
        for (int i = 0; i < 2; i++) {
            const int idx = i * 256 + tid;
            const int br = idx >> 4, bc4 = (idx & 15) * 4;
            cp_async16(Bs[buf] + br * BLD + bc4, Bb + (size_t)(k0 + br) * ldb + bc4);
        }
        CP_COMMIT();
    };

    cp_tile(0, 0);

    const int nch = K >> 5;
    for (int ch = 0; ch < nch; ch++) {
        const int buf = ch & 1;

        CP_WAIT0();          // tile `buf` landed (issued last iteration)
        __syncthreads();     // publish across the CTA

        // kick off the next tile; overlaps with the MMA work below.
        // buf^1's readers finished before the barrier above -> safe to overwrite.
        if (ch + 1 < nch) cp_tile((ch + 1) * 32, buf ^ 1);

        const uint32_t* Asb = (const uint32_t*)As[buf];
        const uint32_t* Bsb = (const uint32_t*)Bs[buf];

        #pragma unroll
        for (int ks = 0; ks < 4; ks++) {
            const int k0 = ks * 8;
            uint32_t af[2][4], bf[4][2];
            #pragma unroll
            for (int i = 0; i < 2; i++) {
                const int r0 = wrow + i * 16 + g;
                af[i][0] = tf32r(__uint_as_float(Asb[(r0    ) * ALD + k0 + t]));
                af[i][1] = tf32r(__uint_as_float(Asb[(r0 + 8) * ALD + k0 + t]));
                af[i][2] = tf32r(__uint_as_float(Asb[(r0    ) * ALD + k0 + t + 4]));
                af[i][3] = tf32r(__uint_as_float(Asb[(r0 + 8) * ALD + k0 + t + 4]));
            }
            #pragma unroll
            for (int j = 0; j < 4; j++) {
                const int c = wcol + j * 8 + g;
                bf[j][0] = tf32r(__uint_as_float(Bsb[(k0 + t    ) * BLD + c]));
                bf[j][1] = tf32r(__uint_as_float(Bsb[(k0 + t + 4) * BLD + c]));
            }
            #pragma unroll
            for (int i = 0; i < 2; i++)
                #pragma unroll
                for (int j = 0; j < 4; j++)
                    mma_tf32(acc[i][j], af[i], bf[j]);
        }
        // no trailing barrier: next iteration's CP_WAIT0 + __syncthreads gates reuse
    }

    #pragma unroll
    for (int i = 0; i < 2; i++) {
        const int r0 = brow + wrow + i * 16 + g;
        #pragma unroll
        for (int j = 0; j < 4; j++) {
            const int c = bcol + wcol + j * 8 + 2 * t;
            float b0 = 0.f, b1 = 0.f;
            if (bias) { b0 = bias[c]; b1 = bias[c + 1]; }
            float2 v0 = { acc[i][j][0] + b0, acc[i][j][1] + b1 };
            float2 v1 = { acc[i][j][2] + b0, acc[i][j][3] + b1 };
            *(float2*)(C + (size_t)r0 * ldc + c)       = v0;
            *(float2*)(C + (size_t)(r0 + 8) * ldc + c) = v1;
        }
    }
}

// ===========================================================================
// Tensor-core flash attention v2 (tf32 mma.sync).  UNCHANGED (round-8 WIN)
// ===========================================================================
#define KT    32
#define KPAD  68
#define VPAD  72
#define PPAD  36
#define KS_F  (KT * KPAD)
#define VS_F  (KT * VPAD)
#define BUF_F (KS_F + VS_F)
#define PS_F  (16 * 16 * PPAD)
#define ATT_SM_F     (2 * BUF_F + PS_F)
#define ATT_SM_BYTES (ATT_SM_F * 4) // 72704

__global__ __launch_bounds__(512) void attn_tc(
    const float* __restrict__ Q, const float* __restrict__ KV,
    float* __restrict__ O)
{
    extern __shared__ float asm_[];
    uint32_t* Pb = (uint32_t*)(asm_ + 2 * BUF_F);

    const int tid  = threadIdx.x;
    const int wid  = tid >> 5;
    const int lane = tid & 31;
    const int g    = lane >> 2;
    const int t    = lane & 3;

    const int qt = blockIdx.x;
    const int h  = blockIdx.y;
    const int b  = blockIdx.z;

    const int qrow0  = qt * 256 + wid * 16 + g;
    const size_t qg0 = ((size_t)b * SQ + qrow0) * INNER + h * DHEAD;

    uint32_t qa[8][4];
    {
        const float* q0 = Q + qg0;
        const float* q1 = q0 + 8 * INNER;
        #pragma unroll
        for (int ks = 0; ks < 8; ks++) {
            qa[ks][0] = tf32r(0.125f * q0[8 * ks + t]);
            qa[ks][1] = tf32r(0.125f * q1[8 * ks + t]);
            qa[ks][2] = tf32r(0.125f * q0[8 * ks + t + 4]);
            qa[ks][3] = tf32r(0.125f * q1[8 * ks + t + 4]);
        }
    }

    float m = -INFINITY;
    float l0 = 0.f, l1 = 0.f;
    float o[8][4];
    #pragma unroll
    for (int j = 0; j < 8; j++)
        #pragma unroll
        for (int r = 0; r < 4; r++) o[j][r] = 0.f;

    const int pbase = wid * 16 * PPAD;

    const int ldj  = tid >> 4;
    const int ldd4 = (tid & 15) * 4;
    auto ldtile = [&](int n, float4& kr, float4& vr) {
        const float* p = KV + ((size_t)b * SKV + n * KT + ldj) * (2 * INNER)
                            + h * DHEAD + ldd4;
        kr = *(const float4*)p;
        vr = *(const float4*)(p + INNER);
    };
    auto sttile = [&](int buf, const float4& kr, const float4& vr) {
        uint32_t* kb = (uint32_t*)(asm_ + buf * BUF_F);
        uint32_t* vb = kb + KS_F;
        uint4 uk; uk.x = tf32r(kr.x); uk.y = tf32r(kr.y);
                  uk.z = tf32r(kr.z); uk.w = tf32r(kr.w);
        *(uint4*)(kb + ldj * KPAD + ldd4) = uk;
        uint4 uv; uv.x = tf32r(vr.x); uv.y = tf32r(vr.y);
                  uv.z = tf32r(vr.z); uv.w = tf32r(vr.w);
        *(uint4*)(vb + ldj * VPAD + ldd4) = uv;
    };

    {
        float4 kr, vr;
        ldtile(0, kr, vr);
        sttile(0, kr, vr);
    }
    __syncthreads();

    const int NT = SKV / KT;
    for (int n = 0; n < NT; n++) {
        const int buf = n & 1;

        float4 krn, vrn;
        if (n + 1 < NT) ldtile(n + 1, krn, vrn);

        const uint32_t* Ksb = (const uint32_t*)(asm_ + buf * BUF_F);
        const uint32_t* Vsb = Ksb + KS_F;

        float s[4][4];
        #pragma unroll
        for (int j = 0; j < 4; j++)
            #pragma unroll
            for (int r = 0; r < 4; r++) s[j][r] = 0.f;

        #pragma unroll
        for (int ks = 0; ks < 8; ks++) {
            const int k0 = ks * 8;
            uint32_t bf[4][2];
            #pragma unroll
            for (int j = 0; j < 4; j++) {
                const int nn = j * 8 + g;
                bf[j][0] = Ksb[nn * KPAD + k0 + t];
                bf[j][1] = Ksb[nn * KPAD + k0 + t + 4];
            }
            #pragma unroll
            for (int j = 0; j < 4; j++)
                mma_tf32(s[j], qa[ks], bf[j]);
        }

        float tm = -INFINITY;
        #pragma unroll
        for (int j = 0; j < 4; j++) {
            tm = fmaxf(tm, fmaxf(fmaxf(s[j][0], s[j][1]),
                                 fmaxf(s[j][2], s[j][3])));
        }
        #pragma unroll
        for (int d = 16; d >= 1; d >>= 1)
            tm = fmaxf(tm, __shfl_xor_sync(0xffffffffu, tm, d));

        const float mn = fmaxf(m, tm);
        const float a  = __expf(m - mn);
        if (a < 1.f) {
            l0 *= a; l1 *= a;
            #pragma unroll
            for (int j = 0; j < 8; j++) {
                o[j][0] *= a; o[j][1] *= a; o[j][2] *= a; o[j][3] *= a;
            }
        }
        m = mn;

        float rs0 = 0.f, rs1 = 0.f;
        #pragma unroll
        for (int j = 0; j < 4; j++) {
            const float p0 = __expf(s[j][0] - m);
            const float p1 = __expf(s[j][1] - m);
            const float p2 = __expf(s[j][2] - m);
            const float p3 = __expf(s[j][3] - m);
            rs0 += p0 + p1;
            rs1 += p2 + p3;
            const int c = j * 8 + 2 * t;
            Pb[pbase + g * PPAD + c]           = tf32r(p0);
            Pb[pbase + g * PPAD + c + 1]       = tf32r(p1);
            Pb[pbase + (g + 8) * PPAD + c]     = tf32r(p2);
            Pb[pbase + (g + 8) * PPAD + c + 1] = tf32r(p3);
        }
        rs0 += __shfl_xor_sync(0xffffffffu, rs0, 1);
        rs0 += __shfl_xor_sync(0xffffffffu, rs0, 2);
        rs1 += __shfl_xor_sync(0xffffffffu, rs1, 1);
        rs1 += __shfl_xor_sync(0xffffffffu, rs1, 2);
        l0 += rs0; l1 += rs1;

        __syncwarp();

        #pragma unroll
        for (int ks = 0; ks < 4; ks++) {
            const int k0 = ks * 8;
            uint32_t pa[4];
            pa[0] = Pb[pbase + g * PPAD + k0 + t];
            pa[1] = Pb[pbase + (g + 8) * PPAD + k0 + t];
            pa[2] = Pb[pbase + g * PPAD + k0 + t + 4];
            pa[3] = Pb[pbase + (g + 8) * PPAD + k0 + t + 4];
            #pragma unroll
            for (int j = 0; j < 8; j++) {
                uint32_t bf[2];
                const int nn = j * 8 + g;
                bf[0] = Vsb[(k0 + t    ) * VPAD + nn];
                bf[1] = Vsb[(k0 + t + 4) * VPAD + nn];
                mma_tf32(o[j], pa, bf);
            }
        }
        __syncwarp();

        if (n + 1 < NT) sttile(buf ^ 1, krn, vrn);
        __syncthreads();
    }

    const float inv0 = 1.f / l0;
    const float inv1 = 1.f / l1;
    float* o0 = O + qg0;
    float* o1 = o0 + 8 * INNER;
    #pragma unroll
    for (int j = 0; j < 8; j++) {
        const int c = j * 8 + 2 * t;
        float2 v0 = { o[j][0] * inv0, o[j][1] * inv0 };
        float2 v1 = { o[j][2] * inv1, o[j][3] * inv1 };
        *(float2*)(o0 + c) = v0;
        *(float2*)(o1 + c) = v1;
    }
}

// ===========================================================================
// kernel_launch
// ===========================================================================
extern "C" void kernel_launch(void* const* d_in, const int* in_sizes, int n_in,
                              void* d_out, int out_size)
{
    const float* x_q   = (const float*)d_in[0];
    const float* x_kv  = (const float*)d_in[1];
    const float* W_qkv = (const float*)d_in[2];  // [1024, 3072]
    const float* W_out = (const float*)d_in[3];  // [1024, 1024]
    const float* b_out = (const float*)d_in[4];  // [1024]
    float* out = (float*)d_out;

    float *q, *kv, *o;
    cudaGetSymbolAddress((void**)&q,  g_q);
    cudaGetSymbolAddress((void**)&kv, g_kv);
    cudaGetSymbolAddress((void**)&o,  g_o);

    cudaFuncSetAttribute(gemm_tf32mma,
                         cudaFuncAttributeMaxDynamicSharedMemorySize, SM_BYTES);
    cudaFuncSetAttribute(attn_tc,
                         cudaFuncAttributeMaxDynamicSharedMemorySize, ATT_SM_BYTES);

    // Q = x_q @ W_qkv[:, 0:1024]             -> [4096, 1024]
    gemm_tf32mma<<<dim3(INNER / 64, MQ / 128), 256, SM_BYTES>>>(
        x_q, W_qkv, q, nullptr, DIM, DIM, 3 * INNER, INNER);

    // KV = x_kv @ W_qkv[:, 1024:3072]        -> [4096, 2048]  (K | V)
    gemm_tf32mma<<<dim3(2 * INNER / 64, MKV / 128), 256, SM_BYTES>>>(
        x_kv, W_qkv + INNER, kv, nullptr, DIM, DIM, 3 * INNER, 2 * INNER);

    // attention (tensor core, fa2)            -> O [4096, 1024]
    attn_tc<<<dim3(SQ / 256, HEADS, BATCH), 512, ATT_SM_BYTES>>>(q, kv, o);

    // out = O @ W_out + b_out                 -> [4096, 1024]
    gemm_tf32mma<<<dim3(DIM / 64, MQ / 128), 256, SM_BYTES>>>(
        o, W_out, out, b_out, INNER, INNER, INNER, DIM);
}

// round 12
// speedup vs baseline: 1.1866x; 1.0423x over previous
#include <cuda_runtime.h>
#include <cstdint>
#include <math.h>

// Problem constants (fixed by the dataset)
#define BATCH   2
#define SQ      2048
#define SKV     2048
#define DIM     1024
#define HEADS   16
#define DHEAD   64
#define INNER   1024            // HEADS * DIM_HEAD
#define MQ      (BATCH * SQ)    // 4096
#define MKV     (BATCH * SKV)   // 4096

// Scratch (no cudaMalloc allowed)
__device__ float g_q  [MQ  * INNER];          // 16 MB
__device__ float g_kv [MKV * 2 * INNER];      // 32 MB (K | V)
__device__ float g_o  [MQ  * INNER];          // 16 MB (pre-rounded by attn epilogue)
__device__ float g_xq [MQ  * DIM];            // 16 MB pre-rounded x_q
__device__ float g_xkv[MKV * DIM];            // 16 MB pre-rounded x_kv
__device__ float g_w  [DIM * 3 * INNER];      // 12 MB pre-rounded W_qkv
__device__ float g_wo [INNER * DIM];          //  4 MB pre-rounded W_out

// fp32 -> tf32 (round-to-nearest) as raw bits
__device__ __forceinline__ uint32_t tf32r(float x) {
    uint32_t r;
    asm("cvt.rna.tf32.f32 %0, %1;" : "=r"(r) : "f"(x));
    return r;
}

// warp-level tf32 MMA: D[16x8] += A[16x8] * B[8x8]  (row.col)
__device__ __forceinline__ void mma_tf32(float* d, const uint32_t* a, const uint32_t* b) {
    asm volatile(
        "mma.sync.aligned.m16n8k8.row.col.f32.tf32.tf32.f32 "
        "{%0,%1,%2,%3}, {%4,%5,%6,%7}, {%8,%9}, {%0,%1,%2,%3};"
        : "+f"(d[0]), "+f"(d[1]), "+f"(d[2]), "+f"(d[3])
        : "r"(a[0]), "r"(a[1]), "r"(a[2]), "r"(a[3]), "r"(b[0]), "r"(b[1]));
}

// async 16B copy gmem -> smem (Ampere+ LDGSTS; family-wide, OK on sm_103)
__device__ __forceinline__ void cp_async16(void* sptr, const void* gptr) {
    uint32_t sa = (uint32_t)__cvta_generic_to_shared(sptr);
    asm volatile("cp.async.cg.shared.global [%0], [%1], 16;" :: "r"(sa), "l"(gptr));
}
#define CP_COMMIT()  asm volatile("cp.async.commit_group;" ::: "memory")
#define CP_WAIT0()   asm volatile("cp.async.wait_group 0;" ::: "memory")

// ===========================================================================
// one-shot tf32 pre-rounding: out[i] = rna_tf32(in[i]), float4 grid-stride
// ===========================================================================
__global__ __launch_bounds__(256) void round_tf32(
    const float* __restrict__ in, float* __restrict__ out, int n4)
{
    const int i = blockIdx.x * 256 + threadIdx.x;
    if (i < n4) {
        float4 v = ((const float4*)in)[i];
        uint4 u;
        u.x = tf32r(v.x); u.y = tf32r(v.y);
        u.z = tf32r(v.z); u.w = tf32r(v.w);
        ((uint4*)out)[i] = u;
    }
}

// ===========================================================================
// tf32 tensor-core GEMM: C[M,N] = A[M,K] @ B[K,N] (+ bias)
// A and B must be PRE-ROUNDED tf32 values (fp32 storage). No cvt in the loop.
// CTA tile 128x64, 256 threads (8 warps, 4x2 grid of 32x32 warp tiles),
// K-tile 32, double buffer via cp.async, ONE sync per chunk, 2 CTAs/SM.
// ===========================================================================
#define ALD 36                   // A smem pitch: frag banks 4g+t, conflict-free
#define BLD 72                   // B smem pitch (72 % 32 == 8): frag banks 8t+g
#define A_TILE_F (128 * ALD)     // 4608
#define B_TILE_F (32 * BLD)      // 2304
#define SM_FLOATS (2 * (A_TILE_F + B_TILE_F))
#define SM_BYTES  (SM_FLOATS * 4)   // 55296

__global__ __launch_bounds__(256, 2) void gemm_tf32mma(
    const float* __restrict__ A, const float* __restrict__ B,
    float* __restrict__ C, const float* __restrict__ bias,
    int K, int lda, int ldb, int ldc)
{
    extern __shared__ float smem[];
    float* As[2] = { smem,            smem + A_TILE_F + B_TILE_F };
    float* Bs[2] = { smem + A_TILE_F, smem + 2 * A_TILE_F + B_TILE_F };

    const int tid  = threadIdx.x;
    const int wid  = tid >> 5;        // 0..7
    const int lane = tid & 31;
    const int g    = lane >> 2;
    const int t    = lane & 3;
    const int wrow = (wid & 3) * 32;  // 4 warp rows
    const int wcol = (wid >> 2) * 32; // 2 warp cols

    const int brow = blockIdx.y * 128;
    const int bcol = blockIdx.x * 64;

    float acc[2][4][4];
    #pragma unroll
    for (int i = 0; i < 2; i++)
        #pragma unroll
        for (int j = 0; j < 4; j++)
            #pragma unroll
            for (int r = 0; r < 4; r++) acc[i][j][r] = 0.f;

    const float* Ab = A + (size_t)brow * lda;
    const float* Bb = B + bcol;

    // A tile: 128x32 = 1024 float4 -> 4 cp/thread; B tile: 32x64 = 512 -> 2 cp/thread
    auto cp_tile = [&](int k0, int buf) {
        #pragma unroll
        for (int i = 0; i < 4; i++) {
            const int idx = i * 256 + tid;
            const int ar = idx >> 3, ac4 = (idx & 7) * 4;
            cp_async16(As[buf] + ar * ALD + ac4, Ab + (size_t)ar * lda + k0 + ac4);
        }
        #pragma unroll
        for (int i = 0; i < 2; i++) {
            const int idx = i * 256 + tid;
            const int br = idx >> 4, bc4 = (idx & 15) * 4;
            cp_async16(Bs[buf] + br * BLD + bc4, Bb + (size_t)(k0 + br) * ldb + bc4);
        }
        CP_COMMIT();
    };

    cp_tile(0, 0);

    const int nch = K >> 5;
    for (int ch = 0; ch < nch; ch++) {
        const int buf = ch & 1;

        CP_WAIT0();          // tile `buf` landed (issued last iteration)
        __syncthreads();     // publish across the CTA

        // kick off the next tile; overlaps with the MMA work below.
        if (ch + 1 < nch) cp_tile((ch + 1) * 32, buf ^ 1);

        const uint32_t* Asb = (const uint32_t*)As[buf];
        const uint32_t* Bsb = (const uint32_t*)Bs[buf];

        #pragma unroll
        for (int ks = 0; ks < 4; ks++) {
            const int k0 = ks * 8;
            uint32_t af[2][4], bf[4][2];
            #pragma unroll
            for (int i = 0; i < 2; i++) {
                const int r0 = wrow + i * 16 + g;
                af[i][0] = Asb[(r0    ) * ALD + k0 + t];
                af[i][1] = Asb[(r0 + 8) * ALD + k0 + t];
                af[i][2] = Asb[(r0    ) * ALD + k0 + t + 4];
                af[i][3] = Asb[(r0 + 8) * ALD + k0 + t + 4];
            }
            #pragma unroll
            for (int j = 0; j < 4; j++) {
                const int c = wcol + j * 8 + g;
                bf[j][0] = Bsb[(k0 + t    ) * BLD + c];
                bf[j][1] = Bsb[(k0 + t + 4) * BLD + c];
            }
            #pragma unroll
            for (int i = 0; i < 2; i++)
                #pragma unroll
                for (int j = 0; j < 4; j++)
                    mma_tf32(acc[i][j], af[i], bf[j]);
        }
        // no trailing barrier: next iteration's CP_WAIT0 + __syncthreads gates reuse
    }

    #pragma unroll
    for (int i = 0; i < 2; i++) {
        const int r0 = brow + wrow + i * 16 + g;
        #pragma unroll
        for (int j = 0; j < 4; j++) {
            const int c = bcol + wcol + j * 8 + 2 * t;
            float b0 = 0.f, b1 = 0.f;
            if (bias) { b0 = bias[c]; b1 = bias[c + 1]; }
            float2 v0 = { acc[i][j][0] + b0, acc[i][j][1] + b1 };
            float2 v1 = { acc[i][j][2] + b0, acc[i][j][3] + b1 };
            *(float2*)(C + (size_t)r0 * ldc + c)       = v0;
            *(float2*)(C + (size_t)(r0 + 8) * ldc + c) = v1;
        }
    }
}

// ===========================================================================
// Tensor-core flash attention v2 (tf32 mma.sync).  Round-8 WIN + epilogue
// now emits tf32-pre-rounded O (free pre-rounding for the final GEMM's A).
// ===========================================================================
#define KT    32
#define KPAD  68
#define VPAD  72
#define PPAD  36
#define KS_F  (KT * KPAD)
#define VS_F  (KT * VPAD)
#define BUF_F (KS_F + VS_F)
#define PS_F  (16 * 16 * PPAD)
#define ATT_SM_F     (2 * BUF_F + PS_F)
#define ATT_SM_BYTES (ATT_SM_F * 4) // 72704

__global__ __launch_bounds__(512) void attn_tc(
    const float* __restrict__ Q, const float* __restrict__ KV,
    float* __restrict__ O)
{
    extern __shared__ float asm_[];
    uint32_t* Pb = (uint32_t*)(asm_ + 2 * BUF_F);

    const int tid  = threadIdx.x;
    const int wid  = tid >> 5;
    const int lane = tid & 31;
    const int g    = lane >> 2;
    const int t    = lane & 3;

    const int qt = blockIdx.x;
    const int h  = blockIdx.y;
    const int b  = blockIdx.z;

    const int qrow0  = qt * 256 + wid * 16 + g;
    const size_t qg0 = ((size_t)b * SQ + qrow0) * INNER + h * DHEAD;

    uint32_t qa[8][4];
    {
        const float* q0 = Q + qg0;
        const float* q1 = q0 + 8 * INNER;
        #pragma unroll
        for (int ks = 0; ks < 8; ks++) {
            qa[ks][0] = tf32r(0.125f * q0[8 * ks + t]);
            qa[ks][1] = tf32r(0.125f * q1[8 * ks + t]);
            qa[ks][2] = tf32r(0.125f * q0[8 * ks + t + 4]);
            qa[ks][3] = tf32r(0.125f * q1[8 * ks + t + 4]);
        }
    }

    float m = -INFINITY;
    float l0 = 0.f, l1 = 0.f;
    float o[8][4];
    #pragma unroll
    for (int j = 0; j < 8; j++)
        #pragma unroll
        for (int r = 0; r < 4; r++) o[j][r] = 0.f;

    const int pbase = wid * 16 * PPAD;

    const int ldj  = tid >> 4;
    const int ldd4 = (tid & 15) * 4;
    auto ldtile = [&](int n, float4& kr, float4& vr) {
        const float* p = KV + ((size_t)b * SKV + n * KT + ldj) * (2 * INNER)
                            + h * DHEAD + ldd4;
        kr = *(const float4*)p;
        vr = *(const float4*)(p + INNER);
    };
    auto sttile = [&](int buf, const float4& kr, const float4& vr) {
        uint32_t* kb = (uint32_t*)(asm_ + buf * BUF_F);
        uint32_t* vb = kb + KS_F;
        uint4 uk; uk.x = tf32r(kr.x); uk.y = tf32r(kr.y);
                  uk.z = tf32r(kr.z); uk.w = tf32r(kr.w);
        *(uint4*)(kb + ldj * KPAD + ldd4) = uk;
        uint4 uv; uv.x = tf32r(vr.x); uv.y = tf32r(vr.y);
                  uv.z = tf32r(vr.z); uv.w = tf32r(vr.w);
        *(uint4*)(vb + ldj * VPAD + ldd4) = uv;
    };

    {
        float4 kr, vr;
        ldtile(0, kr, vr);
        sttile(0, kr, vr);
    }
    __syncthreads();

    const int NT = SKV / KT;
    for (int n = 0; n < NT; n++) {
        const int buf = n & 1;

        float4 krn, vrn;
        if (n + 1 < NT) ldtile(n + 1, krn, vrn);

        const uint32_t* Ksb = (const uint32_t*)(asm_ + buf * BUF_F);
        const uint32_t* Vsb = Ksb + KS_F;

        float s[4][4];
        #pragma unroll
        for (int j = 0; j < 4; j++)
            #pragma unroll
            for (int r = 0; r < 4; r++) s[j][r] = 0.f;

        #pragma unroll
        for (int ks = 0; ks < 8; ks++) {
            const int k0 = ks * 8;
            uint32_t bf[4][2];
            #pragma unroll
            for (int j = 0; j < 4; j++) {
                const int nn = j * 8 + g;
                bf[j][0] = Ksb[nn * KPAD + k0 + t];
                bf[j][1] = Ksb[nn * KPAD + k0 + t + 4];
            }
            #pragma unroll
            for (int j = 0; j < 4; j++)
                mma_tf32(s[j], qa[ks], bf[j]);
        }

        float tm = -INFINITY;
        #pragma unroll
        for (int j = 0; j < 4; j++) {
            tm = fmaxf(tm, fmaxf(fmaxf(s[j][0], s[j][1]),
                                 fmaxf(s[j][2], s[j][3])));
        }
        #pragma unroll
        for (int d = 16; d >= 1; d >>= 1)
            tm = fmaxf(tm, __shfl_xor_sync(0xffffffffu, tm, d));

        const float mn = fmaxf(m, tm);
        const float a  = __expf(m - mn);
        if (a < 1.f) {
            l0 *= a; l1 *= a;
            #pragma unroll
            for (int j = 0; j < 8; j++) {
                o[j][0] *= a; o[j][1] *= a; o[j][2] *= a; o[j][3] *= a;
            }
        }
        m = mn;

        float rs0 = 0.f, rs1 = 0.f;
        #pragma unroll
        for (int j = 0; j < 4; j++) {
            const float p0 = __expf(s[j][0] - m);
            const float p1 = __expf(s[j][1] - m);
            const float p2 = __expf(s[j][2] - m);
            const float p3 = __expf(s[j][3] - m);
            rs0 += p0 + p1;
            rs1 += p2 + p3;
            const int c = j * 8 + 2 * t;
            Pb[pbase + g * PPAD + c]           = tf32r(p0);
            Pb[pbase + g * PPAD + c + 1]       = tf32r(p1);
            Pb[pbase + (g + 8) * PPAD + c]     = tf32r(p2);
            Pb[pbase + (g + 8) * PPAD + c + 1] = tf32r(p3);
        }
        rs0 += __shfl_xor_sync(0xffffffffu, rs0, 1);
        rs0 += __shfl_xor_sync(0xffffffffu, rs0, 2);
        rs1 += __shfl_xor_sync(0xffffffffu, rs1, 1);
        rs1 += __shfl_xor_sync(0xffffffffu, rs1, 2);
        l0 += rs0; l1 += rs1;

        __syncwarp();

        #pragma unroll
        for (int ks = 0; ks < 4; ks++) {
            const int k0 = ks * 8;
            uint32_t pa[4];
            pa[0] = Pb[pbase + g * PPAD + k0 + t];
            pa[1] = Pb[pbase + (g + 8) * PPAD + k0 + t];
            pa[2] = Pb[pbase + g * PPAD + k0 + t + 4];
            pa[3] = Pb[pbase + (g + 8) * PPAD + k0 + t + 4];
            #pragma unroll
            for (int j = 0; j < 8; j++) {
                uint32_t bf[2];
                const int nn = j * 8 + g;
                bf[0] = Vsb[(k0 + t    ) * VPAD + nn];
                bf[1] = Vsb[(k0 + t + 4) * VPAD + nn];
                mma_tf32(o[j], pa, bf);
            }
        }
        __syncwarp();

        if (n + 1 < NT) sttile(buf ^ 1, krn, vrn);
        __syncthreads();
    }

    // epilogue: emit tf32-pre-rounded O (GEMM3 consumes it directly)
    const float inv0 = 1.f / l0;
    const float inv1 = 1.f / l1;
    float* o0 = O + qg0;
    float* o1 = o0 + 8 * INNER;
    #pragma unroll
    for (int j = 0; j < 8; j++) {
        const int c = j * 8 + 2 * t;
        uint2 v0 = { tf32r(o[j][0] * inv0), tf32r(o[j][1] * inv0) };
        uint2 v1 = { tf32r(o[j][2] * inv1), tf32r(o[j][3] * inv1) };
        *(uint2*)(o0 + c) = v0;
        *(uint2*)(o1 + c) = v1;
    }
}

// ===========================================================================
// kernel_launch
// ===========================================================================
extern "C" void kernel_launch(void* const* d_in, const int* in_sizes, int n_in,
                              void* d_out, int out_size)
{
    const float* x_q   = (const float*)d_in[0];
    const float* x_kv  = (const float*)d_in[1];
    const float* W_qkv = (const float*)d_in[2];  // [1024, 3072]
    const float* W_out = (const float*)d_in[3];  // [1024, 1024]
    const float* b_out = (const float*)d_in[4];  // [1024]
    float* out = (float*)d_out;

    float *q, *kv, *o, *xq, *xkv, *w, *wo;
    cudaGetSymbolAddress((void**)&q,   g_q);
    cudaGetSymbolAddress((void**)&kv,  g_kv);
    cudaGetSymbolAddress((void**)&o,   g_o);
    cudaGetSymbolAddress((void**)&xq,  g_xq);
    cudaGetSymbolAddress((void**)&xkv, g_xkv);
    cudaGetSymbolAddress((void**)&w,   g_w);
    cudaGetSymbolAddress((void**)&wo,  g_wo);

    cudaFuncSetAttribute(gemm_tf32mma,
                         cudaFuncAttributeMaxDynamicSharedMemorySize, SM_BYTES);
    cudaFuncSetAttribute(attn_tc,
                         cudaFuncAttributeMaxDynamicSharedMemorySize, ATT_SM_BYTES);

    // one-shot tf32 pre-rounding of all GEMM operands
    round_tf32<<<(MQ * DIM / 4 + 255) / 256, 256>>>(x_q,  xq,  MQ * DIM / 4);
    round_tf32<<<(MKV * DIM / 4 + 255) / 256, 256>>>(x_kv, xkv, MKV * DIM / 4);
    round_tf32<<<(DIM * 3 * INNER / 4 + 255) / 256, 256>>>(W_qkv, w, DIM * 3 * INNER / 4);
    round_tf32<<<(INNER * DIM / 4 + 255) / 256, 256>>>(W_out, wo, INNER * DIM / 4);

    // Q = x_q @ W_qkv[:, 0:1024]             -> [4096, 1024]
    gemm_tf32mma<<<dim3(INNER / 64, MQ / 128), 256, SM_BYTES>>>(
        xq, w, q, nullptr, DIM, DIM, 3 * INNER, INNER);

    // KV = x_kv @ W_qkv[:, 1024:3072]        -> [4096, 2048]  (K | V)
    gemm_tf32mma<<<dim3(2 * INNER / 64, MKV / 128), 256, SM_BYTES>>>(
        xkv, w + INNER, kv, nullptr, DIM, DIM, 3 * INNER, 2 * INNER);

    // attention (tensor core, fa2)            -> O [4096, 1024] (tf32-rounded)
    attn_tc<<<dim3(SQ / 256, HEADS, BATCH), 512, ATT_SM_BYTES>>>(q, kv, o);

    // out = O @ W_out + b_out                 -> [4096, 1024]
    gemm_tf32mma<<<dim3(DIM / 64, MQ / 128), 256, SM_BYTES>>>(
        o, wo, out, b_out, INNER, INNER, INNER, DIM);
}

// round 13
// speedup vs baseline: 1.2868x; 1.0844x over previous
#include <cuda_runtime.h>
#include <cstdint>
#include <math.h>

// Problem constants (fixed by the dataset)
#define BATCH   2
#define SQ      2048
#define SKV     2048
#define DIM     1024
#define HEADS   16
#define DHEAD   64
#define INNER   1024            // HEADS * DIM_HEAD
#define MQ      (BATCH * SQ)    // 4096
#define MKV     (BATCH * SKV)   // 4096

// Scratch (no cudaMalloc allowed)
__device__ float g_q  [MQ  * INNER];          // 16 MB
__device__ float g_kv [MKV * 2 * INNER];      // 32 MB (K | V)
__device__ float g_o  [MQ  * INNER];          // 16 MB (pre-rounded by attn epilogue)
__device__ float g_xq [MQ  * DIM];            // 16 MB pre-rounded x_q
__device__ float g_xkv[MKV * DIM];            // 16 MB pre-rounded x_kv
__device__ float g_w  [DIM * 3 * INNER];      // 12 MB pre-rounded W_qkv
__device__ float g_wo [INNER * DIM];          //  4 MB pre-rounded W_out

// fp32 -> tf32 (round-to-nearest) as raw bits
__device__ __forceinline__ uint32_t tf32r(float x) {
    uint32_t r;
    asm("cvt.rna.tf32.f32 %0, %1;" : "=r"(r) : "f"(x));
    return r;
}

// warp-level tf32 MMA: D[16x8] += A[16x8] * B[8x8]  (row.col)
__device__ __forceinline__ void mma_tf32(float* d, const uint32_t* a, const uint32_t* b) {
    asm volatile(
        "mma.sync.aligned.m16n8k8.row.col.f32.tf32.tf32.f32 "
        "{%0,%1,%2,%3}, {%4,%5,%6,%7}, {%8,%9}, {%0,%1,%2,%3};"
        : "+f"(d[0]), "+f"(d[1]), "+f"(d[2]), "+f"(d[3])
        : "r"(a[0]), "r"(a[1]), "r"(a[2]), "r"(a[3]), "r"(b[0]), "r"(b[1]));
}

// async 16B copy gmem -> smem (Ampere+ LDGSTS; family-wide, OK on sm_103)
__device__ __forceinline__ void cp_async16(void* sptr, const void* gptr) {
    uint32_t sa = (uint32_t)__cvta_generic_to_shared(sptr);
    asm volatile("cp.async.cg.shared.global [%0], [%1], 16;" :: "r"(sa), "l"(gptr));
}
#define CP_COMMIT()  asm volatile("cp.async.commit_group;" ::: "memory")
#define CP_WAIT0()   asm volatile("cp.async.wait_group 0;" ::: "memory")

// ===========================================================================
// one-shot tf32 pre-rounding: out[i] = rna_tf32(in[i])
// ===========================================================================
__global__ __launch_bounds__(256) void round_tf32(
    const float* __restrict__ in, float* __restrict__ out, int n4)
{
    const int i = blockIdx.x * 256 + threadIdx.x;
    if (i < n4) {
        float4 v = ((const float4*)in)[i];
        uint4 u;
        u.x = tf32r(v.x); u.y = tf32r(v.y);
        u.z = tf32r(v.z); u.w = tf32r(v.w);
        ((uint4*)out)[i] = u;
    }
}

// ===========================================================================
// tf32 tensor-core GEMM: C[M,N] = A[M,K] @ B[K,N] (+ bias)
// Operands PRE-ROUNDED tf32 (fp32 storage) -> no cvt in the loop.
// CTA tile 128x128, 256 threads (8 warps, 2x4 grid of 64x32 warp tiles):
// A-fragment reuse across 4 n-subtiles cuts smem crossbar traffic to
// 192 B/MMA (was 256). K-tile 32, cp.async double buffer, ONE sync per
// chunk, 2 CTAs/SM for barrier decoupling.
// ===========================================================================
#define ALD 36                   // A smem pitch: frag banks 4g+t, conflict-free
#define BLD 136                  // B smem pitch (136 % 32 == 8): frag banks 8t+g
#define A_TILE_F (128 * ALD)     // 4608
#define B_TILE_F (32 * BLD)      // 4352
#define SM_FLOATS (2 * (A_TILE_F + B_TILE_F))
#define SM_BYTES  (SM_FLOATS * 4)   // 71680

__global__ __launch_bounds__(256, 2) void gemm_tf32mma(
    const float* __restrict__ A, const float* __restrict__ B,
    float* __restrict__ C, const float* __restrict__ bias,
    int K, int lda, int ldb, int ldc)
{
    extern __shared__ float smem[];
    float* As[2] = { smem,            smem + A_TILE_F + B_TILE_F };
    float* Bs[2] = { smem + A_TILE_F, smem + 2 * A_TILE_F + B_TILE_F };

    const int tid  = threadIdx.x;
    const int wid  = tid >> 5;        // 0..7
    const int lane = tid & 31;
    const int g    = lane >> 2;
    const int t    = lane & 3;
    const int wrow = (wid & 1) * 64;  // 2 warp rows (64 each)
    const int wcol = (wid >> 1) * 32; // 4 warp cols (32 each)

    const int brow = blockIdx.y * 128;
    const int bcol = blockIdx.x * 128;

    float acc[4][4][4];
    #pragma unroll
    for (int i = 0; i < 4; i++)
        #pragma unroll
        for (int j = 0; j < 4; j++)
            #pragma unroll
            for (int r = 0; r < 4; r++) acc[i][j][r] = 0.f;

    const float* Ab = A + (size_t)brow * lda;
    const float* Bb = B + bcol;

    // A tile: 128x32 = 1024 float4; B tile: 32x128 = 1024 float4; 4 cp each/thread
    auto cp_tile = [&](int k0, int buf) {
        #pragma unroll
        for (int i = 0; i < 4; i++) {
            const int idx = i * 256 + tid;
            const int ar = idx >> 3, ac4 = (idx & 7) * 4;
            cp_async16(As[buf] + ar * ALD + ac4, Ab + (size_t)ar * lda + k0 + ac4);
            const int br = idx >> 5, bc4 = (idx & 31) * 4;
            cp_async16(Bs[buf] + br * BLD + bc4, Bb + (size_t)(k0 + br) * ldb + bc4);
        }
        CP_COMMIT();
    };

    cp_tile(0, 0);

    const int nch = K >> 5;
    for (int ch = 0; ch < nch; ch++) {
        const int buf = ch & 1;

        CP_WAIT0();          // tile `buf` landed (issued last iteration)
        __syncthreads();     // publish across the CTA

        // kick off the next tile; overlaps with the MMA work below.
        if (ch + 1 < nch) cp_tile((ch + 1) * 32, buf ^ 1);

        const uint32_t* Asb = (const uint32_t*)As[buf];
        const uint32_t* Bsb = (const uint32_t*)Bs[buf];

        #pragma unroll
        for (int ks = 0; ks < 4; ks++) {
            const int k0 = ks * 8;
            uint32_t af[4][4], bf[4][2];
            #pragma unroll
            for (int i = 0; i < 4; i++) {
                const int r0 = wrow + i * 16 + g;
                af[i][0] = Asb[(r0    ) * ALD + k0 + t];
                af[i][1] = Asb[(r0 + 8) * ALD + k0 + t];
                af[i][2] = Asb[(r0    ) * ALD + k0 + t + 4];
                af[i][3] = Asb[(r0 + 8) * ALD + k0 + t + 4];
            }
            #pragma unroll
            for (int j = 0; j < 4; j++) {
                const int c = wcol + j * 8 + g;
                bf[j][0] = Bsb[(k0 + t    ) * BLD + c];
                bf[j][1] = Bsb[(k0 + t + 4) * BLD + c];
            }
            #pragma unroll
            for (int i = 0; i < 4; i++)
                #pragma unroll
                for (int j = 0; j < 4; j++)
                    mma_tf32(acc[i][j], af[i], bf[j]);
        }
        // no trailing barrier: next iteration's CP_WAIT0 + __syncthreads gates reuse
    }

    #pragma unroll
    for (int i = 0; i < 4; i++) {
        const int r0 = brow + wrow + i * 16 + g;
        #pragma unroll
        for (int j = 0; j < 4; j++) {
            const int c = bcol + wcol + j * 8 + 2 * t;
            float b0 = 0.f, b1 = 0.f;
            if (bias) { b0 = bias[c]; b1 = bias[c + 1]; }
            float2 v0 = { acc[i][j][0] + b0, acc[i][j][1] + b1 };
            float2 v1 = { acc[i][j][2] + b0, acc[i][j][3] + b1 };
            *(float2*)(C + (size_t)r0 * ldc + c)       = v0;
            *(float2*)(C + (size_t)(r0 + 8) * ldc + c) = v1;
        }
    }
}

// ===========================================================================
// Tensor-core flash attention v2 (tf32 mma.sync).  UNCHANGED (round-8 WIN,
// epilogue emits tf32-pre-rounded O for the final GEMM).
// ===========================================================================
#define KT    32
#define KPAD  68
#define VPAD  72
#define PPAD  36
#define KS_F  (KT * KPAD)
#define VS_F  (KT * VPAD)
#define BUF_F (KS_F + VS_F)
#define PS_F  (16 * 16 * PPAD)
#define ATT_SM_F     (2 * BUF_F + PS_F)
#define ATT_SM_BYTES (ATT_SM_F * 4) // 72704

__global__ __launch_bounds__(512) void attn_tc(
    const float* __restrict__ Q, const float* __restrict__ KV,
    float* __restrict__ O)
{
    extern __shared__ float asm_[];
    uint32_t* Pb = (uint32_t*)(asm_ + 2 * BUF_F);

    const int tid  = threadIdx.x;
    const int wid  = tid >> 5;
    const int lane = tid & 31;
    const int g    = lane >> 2;
    const int t    = lane & 3;

    const int qt = blockIdx.x;
    const int h  = blockIdx.y;
    const int b  = blockIdx.z;

    const int qrow0  = qt * 256 + wid * 16 + g;
    const size_t qg0 = ((size_t)b * SQ + qrow0) * INNER + h * DHEAD;

    uint32_t qa[8][4];
    {
        const float* q0 = Q + qg0;
        const float* q1 = q0 + 8 * INNER;
        #pragma unroll
        for (int ks = 0; ks < 8; ks++) {
            qa[ks][0] = tf32r(0.125f * q0[8 * ks + t]);
            qa[ks][1] = tf32r(0.125f * q1[8 * ks + t]);
            qa[ks][2] = tf32r(0.125f * q0[8 * ks + t + 4]);
            qa[ks][3] = tf32r(0.125f * q1[8 * ks + t + 4]);
        }
    }

    float m = -INFINITY;
    float l0 = 0.f, l1 = 0.f;
    float o[8][4];
    #pragma unroll
    for (int j = 0; j < 8; j++)
        #pragma unroll
        for (int r = 0; r < 4; r++) o[j][r] = 0.f;

    const int pbase = wid * 16 * PPAD;

    const int ldj  = tid >> 4;
    const int ldd4 = (tid & 15) * 4;
    auto ldtile = [&](int n, float4& kr, float4& vr) {
        const float* p = KV + ((size_t)b * SKV + n * KT + ldj) * (2 * INNER)
                            + h * DHEAD + ldd4;
        kr = *(const float4*)p;
        vr = *(const float4*)(p + INNER);
    };
    auto sttile = [&](int buf, const float4& kr, const float4& vr) {
        uint32_t* kb = (uint32_t*)(asm_ + buf * BUF_F);
        uint32_t* vb = kb + KS_F;
        uint4 uk; uk.x = tf32r(kr.x); uk.y = tf32r(kr.y);
                  uk.z = tf32r(kr.z); uk.w = tf32r(kr.w);
        *(uint4*)(kb + ldj * KPAD + ldd4) = uk;
        uint4 uv; uv.x = tf32r(vr.x); uv.y = tf32r(vr.y);
                  uv.z = tf32r(vr.z); uv.w = tf32r(vr.w);
        *(uint4*)(vb + ldj * VPAD + ldd4) = uv;
    };

    {
        float4 kr, vr;
        ldtile(0, kr, vr);
        sttile(0, kr, vr);
    }
    __syncthreads();

    const int NT = SKV / KT;
    for (int n = 0; n < NT; n++) {
        const int buf = n & 1;

        float4 krn, vrn;
        if (n + 1 < NT) ldtile(n + 1, krn, vrn);

        const uint32_t* Ksb = (const uint32_t*)(asm_ + buf * BUF_F);
        const uint32_t* Vsb = Ksb + KS_F;

        float s[4][4];
        #pragma unroll
        for (int j = 0; j < 4; j++)
            #pragma unroll
            for (int r = 0; r < 4; r++) s[j][r] = 0.f;

        #pragma unroll
        for (int ks = 0; ks < 8; ks++) {
            const int k0 = ks * 8;
            uint32_t bf[4][2];
            #pragma unroll
            for (int j = 0; j < 4; j++) {
                const int nn = j * 8 + g;
                bf[j][0] = Ksb[nn * KPAD + k0 + t];
                bf[j][1] = Ksb[nn * KPAD + k0 + t + 4];
            }
            #pragma unroll
            for (int j = 0; j < 4; j++)
                mma_tf32(s[j], qa[ks], bf[j]);
        }

        float tm = -INFINITY;
        #pragma unroll
        for (int j = 0; j < 4; j++) {
            tm = fmaxf(tm, fmaxf(fmaxf(s[j][0], s[j][1]),
                                 fmaxf(s[j][2], s[j][3])));
        }
        #pragma unroll
        for (int d = 16; d >= 1; d >>= 1)
            tm = fmaxf(tm, __shfl_xor_sync(0xffffffffu, tm, d));

        const float mn = fmaxf(m, tm);
        const float a  = __expf(m - mn);
        if (a < 1.f) {
            l0 *= a; l1 *= a;
            #pragma unroll
            for (int j = 0; j < 8; j++) {
                o[j][0] *= a; o[j][1] *= a; o[j][2] *= a; o[j][3] *= a;
            }
        }
        m = mn;

        float rs0 = 0.f, rs1 = 0.f;
        #pragma unroll
        for (int j = 0; j < 4; j++) {
            const float p0 = __expf(s[j][0] - m);
            const float p1 = __expf(s[j][1] - m);
            const float p2 = __expf(s[j][2] - m);
            const float p3 = __expf(s[j][3] - m);
            rs0 += p0 + p1;
            rs1 += p2 + p3;
            const int c = j * 8 + 2 * t;
            Pb[pbase + g * PPAD + c]           = tf32r(p0);
            Pb[pbase + g * PPAD + c + 1]       = tf32r(p1);
            Pb[pbase + (g + 8) * PPAD + c]     = tf32r(p2);
            Pb[pbase + (g + 8) * PPAD + c + 1] = tf32r(p3);
        }
        rs0 += __shfl_xor_sync(0xffffffffu, rs0, 1);
        rs0 += __shfl_xor_sync(0xffffffffu, rs0, 2);
        rs1 += __shfl_xor_sync(0xffffffffu, rs1, 1);
        rs1 += __shfl_xor_sync(0xffffffffu, rs1, 2);
        l0 += rs0; l1 += rs1;

        __syncwarp();

        #pragma unroll
        for (int ks = 0; ks < 4; ks++) {
            const int k0 = ks * 8;
            uint32_t pa[4];
            pa[0] = Pb[pbase + g * PPAD + k0 + t];
            pa[1] = Pb[pbase + (g + 8) * PPAD + k0 + t];
            pa[2] = Pb[pbase + g * PPAD + k0 + t + 4];
            pa[3] = Pb[pbase + (g + 8) * PPAD + k0 + t + 4];
            #pragma unroll
            for (int j = 0; j < 8; j++) {
                uint32_t bf[2];
                const int nn = j * 8 + g;
                bf[0] = Vsb[(k0 + t    ) * VPAD + nn];
                bf[1] = Vsb[(k0 + t + 4) * VPAD + nn];
                mma_tf32(o[j], pa, bf);
            }
        }
        __syncwarp();

        if (n + 1 < NT) sttile(buf ^ 1, krn, vrn);
        __syncthreads();
    }

    // epilogue: emit tf32-pre-rounded O (GEMM3 consumes it directly)
    const float inv0 = 1.f / l0;
    const float inv1 = 1.f / l1;
    float* o0 = O + qg0;
    float* o1 = o0 + 8 * INNER;
    #pragma unroll
    for (int j = 0; j < 8; j++) {
        const int c = j * 8 + 2 * t;
        uint2 v0 = { tf32r(o[j][0] * inv0), tf32r(o[j][1] * inv0) };
        uint2 v1 = { tf32r(o[j][2] * inv1), tf32r(o[j][3] * inv1) };
        *(uint2*)(o0 + c) = v0;
        *(uint2*)(o1 + c) = v1;
    }
}

// ===========================================================================
// kernel_launch
// ===========================================================================
extern "C" void kernel_launch(void* const* d_in, const int* in_sizes, int n_in,
                              void* d_out, int out_size)
{
    const float* x_q   = (const float*)d_in[0];
    const float* x_kv  = (const float*)d_in[1];
    const float* W_qkv = (const float*)d_in[2];  // [1024, 3072]
    const float* W_out = (const float*)d_in[3];  // [1024, 1024]
    const float* b_out = (const float*)d_in[4];  // [1024]
    float* out = (float*)d_out;

    float *q, *kv, *o, *xq, *xkv, *w, *wo;
    cudaGetSymbolAddress((void**)&q,   g_q);
    cudaGetSymbolAddress((void**)&kv,  g_kv);
    cudaGetSymbolAddress((void**)&o,   g_o);
    cudaGetSymbolAddress((void**)&xq,  g_xq);
    cudaGetSymbolAddress((void**)&xkv, g_xkv);
    cudaGetSymbolAddress((void**)&w,   g_w);
    cudaGetSymbolAddress((void**)&wo,  g_wo);

    cudaFuncSetAttribute(gemm_tf32mma,
                         cudaFuncAttributeMaxDynamicSharedMemorySize, SM_BYTES);
    cudaFuncSetAttribute(attn_tc,
                         cudaFuncAttributeMaxDynamicSharedMemorySize, ATT_SM_BYTES);

    // one-shot tf32 pre-rounding of all GEMM operands
    round_tf32<<<(MQ * DIM / 4 + 255) / 256, 256>>>(x_q,  xq,  MQ * DIM / 4);
    round_tf32<<<(MKV * DIM / 4 + 255) / 256, 256>>>(x_kv, xkv, MKV * DIM / 4);
    round_tf32<<<(DIM * 3 * INNER / 4 + 255) / 256, 256>>>(W_qkv, w, DIM * 3 * INNER / 4);
    round_tf32<<<(INNER * DIM / 4 + 255) / 256, 256>>>(W_out, wo, INNER * DIM / 4);

    // Q = x_q @ W_qkv[:, 0:1024]             -> [4096, 1024]
    gemm_tf32mma<<<dim3(INNER / 128, MQ / 128), 256, SM_BYTES>>>(
        xq, w, q, nullptr, DIM, DIM, 3 * INNER, INNER);

    // KV = x_kv @ W_qkv[:, 1024:3072]        -> [4096, 2048]  (K | V)
    gemm_tf32mma<<<dim3(2 * INNER / 128, MKV / 128), 256, SM_BYTES>>>(
        xkv, w + INNER, kv, nullptr, DIM, DIM, 3 * INNER, 2 * INNER);

    // attention (tensor core, fa2)            -> O [4096, 1024] (tf32-rounded)
    attn_tc<<<dim3(SQ / 256, HEADS, BATCH), 512, ATT_SM_BYTES>>>(q, kv, o);

    // out = O @ W_out + b_out                 -> [4096, 1024]
    gemm_tf32mma<<<dim3(DIM / 128, MQ / 128), 256, SM_BYTES>>>(
        o, wo, out, b_out, INNER, INNER, INNER, DIM);
}

// round 14
// speedup vs baseline: 1.4150x; 1.0996x over previous
#include <cuda_runtime.h>
#include <cstdint>
#include <math.h>

// Problem constants (fixed by the dataset)
#define BATCH   2
#define SQ      2048
#define SKV     2048
#define DIM     1024
#define HEADS   16
#define DHEAD   64
#define INNER   1024            // HEADS * DIM_HEAD
#define MQ      (BATCH * SQ)    // 4096
#define MKV     (BATCH * SKV)   // 4096

// Scratch (no cudaMalloc allowed)
__device__ float g_q  [MQ  * INNER];          // 16 MB
__device__ float g_kv [MKV * 2 * INNER];      // 32 MB (K | V)
__device__ float g_o  [MQ  * INNER];          // 16 MB (pre-rounded by attn epilogue)
__device__ float g_xq [MQ  * DIM];            // 16 MB pre-rounded x_q
__device__ float g_xkv[MKV * DIM];            // 16 MB pre-rounded x_kv
__device__ float g_w  [DIM * 3 * INNER];      // 12 MB pre-rounded W_qkv
__device__ float g_wo [INNER * DIM];          //  4 MB pre-rounded W_out

// fp32 -> tf32 (round-to-nearest) as raw bits
__device__ __forceinline__ uint32_t tf32r(float x) {
    uint32_t r;
    asm("cvt.rna.tf32.f32 %0, %1;" : "=r"(r) : "f"(x));
    return r;
}

// warp-level tf32 MMA: D[16x8] += A[16x8] * B[8x8]  (row.col)
__device__ __forceinline__ void mma_tf32(float* d, const uint32_t* a, const uint32_t* b) {
    asm volatile(
        "mma.sync.aligned.m16n8k8.row.col.f32.tf32.tf32.f32 "
        "{%0,%1,%2,%3}, {%4,%5,%6,%7}, {%8,%9}, {%0,%1,%2,%3};"
        : "+f"(d[0]), "+f"(d[1]), "+f"(d[2]), "+f"(d[3])
        : "r"(a[0]), "r"(a[1]), "r"(a[2]), "r"(a[3]), "r"(b[0]), "r"(b[1]));
}

// async 16B copy gmem -> smem (Ampere+ LDGSTS; family-wide, OK on sm_103)
__device__ __forceinline__ void cp_async16(void* sptr, const void* gptr) {
    uint32_t sa = (uint32_t)__cvta_generic_to_shared(sptr);
    asm volatile("cp.async.cg.shared.global [%0], [%1], 16;" :: "r"(sa), "l"(gptr));
}
#define CP_COMMIT()  asm volatile("cp.async.commit_group;" ::: "memory")
#define CP_WAIT0()   asm volatile("cp.async.wait_group 0;" ::: "memory")

// ===========================================================================
// one-shot tf32 pre-rounding: out[i] = rna_tf32(in[i])
// ===========================================================================
__global__ __launch_bounds__(256) void round_tf32(
    const float* __restrict__ in, float* __restrict__ out, int n4)
{
    const int i = blockIdx.x * 256 + threadIdx.x;
    if (i < n4) {
        float4 v = ((const float4*)in)[i];
        uint4 u;
        u.x = tf32r(v.x); u.y = tf32r(v.y);
        u.z = tf32r(v.z); u.w = tf32r(v.w);
        ((uint4*)out)[i] = u;
    }
}

// ===========================================================================
// Shared GEMM body: 128x128 CTA tile, 256 threads (8 warps, 2x4 grid of
// 64x32 warp tiles), K-tile 32, cp.async double buffer, ONE sync per chunk.
// Operands pre-rounded tf32. Ab = A + brow*lda, Bb = B + bcol,
// Cb = C + brow*ldc + bcol, biasp = bias + bcol (or null).
// ===========================================================================
#define ALD 36                   // A smem pitch: frag banks 4g+t, conflict-free
#define BLD 136                  // B smem pitch (136 % 32 == 8): frag banks 8t+g
#define A_TILE_F (128 * ALD)     // 4608
#define B_TILE_F (32 * BLD)      // 4352
#define SM_FLOATS (2 * (A_TILE_F + B_TILE_F))
#define SM_BYTES  (SM_FLOATS * 4)   // 71680

__device__ __forceinline__ void gemm_body(
    const float* __restrict__ Ab, const float* __restrict__ Bb,
    float* __restrict__ Cb, const float* __restrict__ biasp,
    int K, int lda, int ldb, int ldc, float* smem)
{
    float* As[2] = { smem,            smem + A_TILE_F + B_TILE_F };
    float* Bs[2] = { smem + A_TILE_F, smem + 2 * A_TILE_F + B_TILE_F };

    const int tid  = threadIdx.x;
    const int wid  = tid >> 5;        // 0..7
    const int lane = tid & 31;
    const int g    = lane >> 2;
    const int t    = lane & 3;
    const int wrow = (wid & 1) * 64;  // 2 warp rows (64 each)
    const int wcol = (wid >> 1) * 32; // 4 warp cols (32 each)

    float acc[4][4][4];
    #pragma unroll
    for (int i = 0; i < 4; i++)
        #pragma unroll
        for (int j = 0; j < 4; j++)
            #pragma unroll
            for (int r = 0; r < 4; r++) acc[i][j][r] = 0.f;

    // A tile: 128x32 = 1024 float4; B tile: 32x128 = 1024 float4; 4 cp each/thread
    auto cp_tile = [&](int k0, int buf) {
        #pragma unroll
        for (int i = 0; i < 4; i++) {
            const int idx = i * 256 + tid;
            const int ar = idx >> 3, ac4 = (idx & 7) * 4;
            cp_async16(As[buf] + ar * ALD + ac4, Ab + (size_t)ar * lda + k0 + ac4);
            const int br = idx >> 5, bc4 = (idx & 31) * 4;
            cp_async16(Bs[buf] + br * BLD + bc4, Bb + (size_t)(k0 + br) * ldb + bc4);
        }
        CP_COMMIT();
    };

    cp_tile(0, 0);

    const int nch = K >> 5;
    for (int ch = 0; ch < nch; ch++) {
        const int buf = ch & 1;

        CP_WAIT0();          // tile `buf` landed (issued last iteration)
        __syncthreads();     // publish across the CTA

        if (ch + 1 < nch) cp_tile((ch + 1) * 32, buf ^ 1);

        const uint32_t* Asb = (const uint32_t*)As[buf];
        const uint32_t* Bsb = (const uint32_t*)Bs[buf];

        #pragma unroll
        for (int ks = 0; ks < 4; ks++) {
            const int k0 = ks * 8;
            uint32_t af[4][4], bf[4][2];
            #pragma unroll
            for (int i = 0; i < 4; i++) {
                const int r0 = wrow + i * 16 + g;
                af[i][0] = Asb[(r0    ) * ALD + k0 + t];
                af[i][1] = Asb[(r0 + 8) * ALD + k0 + t];
                af[i][2] = Asb[(r0    ) * ALD + k0 + t + 4];
                af[i][3] = Asb[(r0 + 8) * ALD + k0 + t + 4];
            }
            #pragma unroll
            for (int j = 0; j < 4; j++) {
                const int c = wcol + j * 8 + g;
                bf[j][0] = Bsb[(k0 + t    ) * BLD + c];
                bf[j][1] = Bsb[(k0 + t + 4) * BLD + c];
            }
            #pragma unroll
            for (int i = 0; i < 4; i++)
                #pragma unroll
                for (int j = 0; j < 4; j++)
                    mma_tf32(acc[i][j], af[i], bf[j]);
        }
    }

    #pragma unroll
    for (int i = 0; i < 4; i++) {
        const int r0 = wrow + i * 16 + g;
        #pragma unroll
        for (int j = 0; j < 4; j++) {
            const int c = wcol + j * 8 + 2 * t;
            float b0 = 0.f, b1 = 0.f;
            if (biasp) { b0 = biasp[c]; b1 = biasp[c + 1]; }
            float2 v0 = { acc[i][j][0] + b0, acc[i][j][1] + b1 };
            float2 v1 = { acc[i][j][2] + b0, acc[i][j][3] + b1 };
            *(float2*)(Cb + (size_t)r0 * ldc + c)       = v0;
            *(float2*)(Cb + (size_t)(r0 + 8) * ldc + c) = v1;
        }
    }
}

// Fused Q+KV projection: one launch, per-block routing.
// grid (24, 32): bx<8 -> Q tile, bx>=8 -> KV tile.
__global__ __launch_bounds__(256, 2) void gemm_qkv(
    const float* __restrict__ xq, const float* __restrict__ xkv,
    const float* __restrict__ w, float* __restrict__ q, float* __restrict__ kv)
{
    extern __shared__ float smem[];
    const int brow = blockIdx.y * 128;
    const int bx   = blockIdx.x;

    const float* A; float* C; int ldc_; int bcol; int wcol;
    if (bx < INNER / 128) {
        A = xq;  C = q;  ldc_ = INNER;     bcol = bx * 128;               wcol = bcol;
    } else {
        A = xkv; C = kv; ldc_ = 2 * INNER; bcol = (bx - INNER / 128) * 128; wcol = INNER + bcol;
    }
    gemm_body(A + (size_t)brow * DIM, w + wcol,
              C + (size_t)brow * ldc_ + bcol, nullptr,
              DIM, DIM, 3 * INNER, ldc_, smem);
}

// Generic GEMM (used for the output projection)
__global__ __launch_bounds__(256, 2) void gemm_tf32mma(
    const float* __restrict__ A, const float* __restrict__ B,
    float* __restrict__ C, const float* __restrict__ bias,
    int K, int lda, int ldb, int ldc)
{
    extern __shared__ float smem[];
    const int brow = blockIdx.y * 128;
    const int bcol = blockIdx.x * 128;
    gemm_body(A + (size_t)brow * lda, B + bcol,
              C + (size_t)brow * ldc + bcol, bias ? bias + bcol : nullptr,
              K, lda, ldb, ldc, smem);
}

// ===========================================================================
// Tensor-core flash attention v3 (tf32 mma.sync).
// CTA: 256 q-rows x (b,h), 512 threads = 16 warps x 16 rows, KV tiles of 32.
// NEW: P never touches smem. The S C-fragment is reused directly as the PV
// A-fragment under the slot permutation (slot t <-> col 2t, slot t+4 <->
// col 2t+1); V B-fragments are loaded from rows 2t / 2t+1 to match.
// VPAD=68 keeps those reads conflict-free (banks 8t+g / 8t+4+g).
// ===========================================================================
#define KT    32
#define KPAD  68
#define VPAD  68
#define KS_F  (KT * KPAD)
#define VS_F  (KT * VPAD)
#define BUF_F (KS_F + VS_F)         // 4352
#define ATT_SM_F     (2 * BUF_F)
#define ATT_SM_BYTES (ATT_SM_F * 4) // 34816

__global__ __launch_bounds__(512) void attn_tc(
    const float* __restrict__ Q, const float* __restrict__ KV,
    float* __restrict__ O)
{
    extern __shared__ float asm_[];

    const int tid  = threadIdx.x;
    const int wid  = tid >> 5;
    const int lane = tid & 31;
    const int g    = lane >> 2;
    const int t    = lane & 3;

    const int qt = blockIdx.x;
    const int h  = blockIdx.y;
    const int b  = blockIdx.z;

    const int qrow0  = qt * 256 + wid * 16 + g;
    const size_t qg0 = ((size_t)b * SQ + qrow0) * INNER + h * DHEAD;

    uint32_t qa[8][4];
    {
        const float* q0 = Q + qg0;
        const float* q1 = q0 + 8 * INNER;
        #pragma unroll
        for (int ks = 0; ks < 8; ks++) {
            qa[ks][0] = tf32r(0.125f * q0[8 * ks + t]);
            qa[ks][1] = tf32r(0.125f * q1[8 * ks + t]);
            qa[ks][2] = tf32r(0.125f * q0[8 * ks + t + 4]);
            qa[ks][3] = tf32r(0.125f * q1[8 * ks + t + 4]);
        }
    }

    float m = -INFINITY;
    float l0 = 0.f, l1 = 0.f;
    float o[8][4];
    #pragma unroll
    for (int j = 0; j < 8; j++)
        #pragma unroll
        for (int r = 0; r < 4; r++) o[j][r] = 0.f;

    const int ldj  = tid >> 4;
    const int ldd4 = (tid & 15) * 4;
    auto ldtile = [&](int n, float4& kr, float4& vr) {
        const float* p = KV + ((size_t)b * SKV + n * KT + ldj) * (2 * INNER)
                            + h * DHEAD + ldd4;
        kr = *(const float4*)p;
        vr = *(const float4*)(p + INNER);
    };
    auto sttile = [&](int buf, const float4& kr, const float4& vr) {
        uint32_t* kb = (uint32_t*)(asm_ + buf * BUF_F);
        uint32_t* vb = kb + KS_F;
        uint4 uk; uk.x = tf32r(kr.x); uk.y = tf32r(kr.y);
                  uk.z = tf32r(kr.z); uk.w = tf32r(kr.w);
        *(uint4*)(kb + ldj * KPAD + ldd4) = uk;
        uint4 uv; uv.x = tf32r(vr.x); uv.y = tf32r(vr.y);
                  uv.z = tf32r(vr.z); uv.w = tf32r(vr.w);
        *(uint4*)(vb + ldj * VPAD + ldd4) = uv;
    };

    {
        float4 kr, vr;
        ldtile(0, kr, vr);
        sttile(0, kr, vr);
    }
    __syncthreads();

    const int NT = SKV / KT;
    for (int n = 0; n < NT; n++) {
        const int buf = n & 1;

        float4 krn, vrn;
        if (n + 1 < NT) ldtile(n + 1, krn, vrn);

        const uint32_t* Ksb = (const uint32_t*)(asm_ + buf * BUF_F);
        const uint32_t* Vsb = Ksb + KS_F;

        // ---- S[16x32] = Q @ K^T  (C-frag: rows g/g+8, cols 2t/2t+1 per j)
        float s[4][4];
        #pragma unroll
        for (int j = 0; j < 4; j++)
            #pragma unroll
            for (int r = 0; r < 4; r++) s[j][r] = 0.f;

        #pragma unroll
        for (int ks = 0; ks < 8; ks++) {
            const int k0 = ks * 8;
            uint32_t bf[4][2];
            #pragma unroll
            for (int j = 0; j < 4; j++) {
                const int nn = j * 8 + g;
                bf[j][0] = Ksb[nn * KPAD + k0 + t];
                bf[j][1] = Ksb[nn * KPAD + k0 + t + 4];
            }
            #pragma unroll
            for (int j = 0; j < 4; j++)
                mma_tf32(s[j], qa[ks], bf[j]);
        }

        // ---- warp-uniform max
        float tm = -INFINITY;
        #pragma unroll
        for (int j = 0; j < 4; j++) {
            tm = fmaxf(tm, fmaxf(fmaxf(s[j][0], s[j][1]),
                                 fmaxf(s[j][2], s[j][3])));
        }
        #pragma unroll
        for (int d = 16; d >= 1; d >>= 1)
            tm = fmaxf(tm, __shfl_xor_sync(0xffffffffu, tm, d));

        const float mn = fmaxf(m, tm);
        const float a  = __expf(m - mn);
        if (a < 1.f) {
            l0 *= a; l1 *= a;
            #pragma unroll
            for (int j = 0; j < 8; j++) {
                o[j][0] *= a; o[j][1] *= a; o[j][2] *= a; o[j][3] *= a;
            }
        }
        m = mn;

        // ---- exp in-register; s[j][r] now holds tf32 P bits
        float rs0 = 0.f, rs1 = 0.f;
        #pragma unroll
        for (int j = 0; j < 4; j++) {
            const float p0 = __expf(s[j][0] - m);
            const float p1 = __expf(s[j][1] - m);
            const float p2 = __expf(s[j][2] - m);
            const float p3 = __expf(s[j][3] - m);
            rs0 += p0 + p1;
            rs1 += p2 + p3;
            s[j][0] = __uint_as_float(tf32r(p0));
            s[j][1] = __uint_as_float(tf32r(p1));
            s[j][2] = __uint_as_float(tf32r(p2));
            s[j][3] = __uint_as_float(tf32r(p3));
        }
        rs0 += __shfl_xor_sync(0xffffffffu, rs0, 1);
        rs0 += __shfl_xor_sync(0xffffffffu, rs0, 2);
        rs1 += __shfl_xor_sync(0xffffffffu, rs1, 1);
        rs1 += __shfl_xor_sync(0xffffffffu, rs1, 2);
        l0 += rs0; l1 += rs1;

        // ---- O[16x64] += P[16x32] @ V[32x64], P straight from registers.
        // A-slot t holds P col k0+2t, slot t+4 holds col k0+2t+1;
        // B-slot t loads V row k0+2t, slot t+4 loads row k0+2t+1.
        #pragma unroll
        for (int ks = 0; ks < 4; ks++) {
            const int k0 = ks * 8;
            uint32_t pa[4];
            pa[0] = __float_as_uint(s[ks][0]);   // P[g   ][k0+2t]
            pa[1] = __float_as_uint(s[ks][2]);   // P[g+8 ][k0+2t]
            pa[2] = __float_as_uint(s[ks][1]);   // P[g   ][k0+2t+1]
            pa[3] = __float_as_uint(s[ks][3]);   // P[g+8 ][k0+2t+1]
            #pragma unroll
            for (int j = 0; j < 8; j++) {
                uint32_t bf[2];
                const int nn = j * 8 + g;
                bf[0] = Vsb[(k0 + 2 * t    ) * VPAD + nn];
                bf[1] = Vsb[(k0 + 2 * t + 1) * VPAD + nn];
                mma_tf32(o[j], pa, bf);
            }
        }

        if (n + 1 < NT) sttile(buf ^ 1, krn, vrn);
        __syncthreads();
    }

    // epilogue: emit tf32-pre-rounded O (final GEMM consumes it directly)
    const float inv0 = 1.f / l0;
    const float inv1 = 1.f / l1;
    float* o0 = O + qg0;
    float* o1 = o0 + 8 * INNER;
    #pragma unroll
    for (int j = 0; j < 8; j++) {
        const int c = j * 8 + 2 * t;
        uint2 v0 = { tf32r(o[j][0] * inv0), tf32r(o[j][1] * inv0) };
        uint2 v1 = { tf32r(o[j][2] * inv1), tf32r(o[j][3] * inv1) };
        *(uint2*)(o0 + c) = v0;
        *(uint2*)(o1 + c) = v1;
    }
}

// ===========================================================================
// kernel_launch
// ===========================================================================
extern "C" void kernel_launch(void* const* d_in, const int* in_sizes, int n_in,
                              void* d_out, int out_size)
{
    const float* x_q   = (const float*)d_in[0];
    const float* x_kv  = (const float*)d_in[1];
    const float* W_qkv = (const float*)d_in[2];  // [1024, 3072]
    const float* W_out = (const float*)d_in[3];  // [1024, 1024]
    const float* b_out = (const float*)d_in[4];  // [1024]
    float* out = (float*)d_out;

    float *q, *kv, *o, *xq, *xkv, *w, *wo;
    cudaGetSymbolAddress((void**)&q,   g_q);
    cudaGetSymbolAddress((void**)&kv,  g_kv);
    cudaGetSymbolAddress((void**)&o,   g_o);
    cudaGetSymbolAddress((void**)&xq,  g_xq);
    cudaGetSymbolAddress((void**)&xkv, g_xkv);
    cudaGetSymbolAddress((void**)&w,   g_w);
    cudaGetSymbolAddress((void**)&wo,  g_wo);

    cudaFuncSetAttribute(gemm_qkv,
                         cudaFuncAttributeMaxDynamicSharedMemorySize, SM_BYTES);
    cudaFuncSetAttribute(gemm_tf32mma,
                         cudaFuncAttributeMaxDynamicSharedMemorySize, SM_BYTES);
    cudaFuncSetAttribute(attn_tc,
                         cudaFuncAttributeMaxDynamicSharedMemorySize, ATT_SM_BYTES);

    // one-shot tf32 pre-rounding of all GEMM operands
    round_tf32<<<(MQ * DIM / 4 + 255) / 256, 256>>>(x_q,  xq,  MQ * DIM / 4);
    round_tf32<<<(MKV * DIM / 4 + 255) / 256, 256>>>(x_kv, xkv, MKV * DIM / 4);
    round_tf32<<<(DIM * 3 * INNER / 4 + 255) / 256, 256>>>(W_qkv, w, DIM * 3 * INNER / 4);
    round_tf32<<<(INNER * DIM / 4 + 255) / 256, 256>>>(W_out, wo, INNER * DIM / 4);

    // [Q | KV] = [x_q | x_kv] @ W_qkv (fused, per-block routing)
    gemm_qkv<<<dim3(3 * INNER / 128, MQ / 128), 256, SM_BYTES>>>(xq, xkv, w, q, kv);

    // attention (tensor core, fa3: P-in-registers)  -> O [4096, 1024]
    attn_tc<<<dim3(SQ / 256, HEADS, BATCH), 512, ATT_SM_BYTES>>>(q, kv, o);

    // out = O @ W_out + b_out                        -> [4096, 1024]
    gemm_tf32mma<<<dim3(DIM / 128, MQ / 128), 256, SM_BYTES>>>(
        o, wo, out, b_out, INNER, INNER, INNER, DIM);
}

// round 15
// speedup vs baseline: 1.5167x; 1.0719x over previous
#include <cuda_runtime.h>
#include <cuda_fp16.h>
#include <cstdint>
#include <math.h>

// Problem constants (fixed by the dataset)
#define BATCH   2
#define SQ      2048
#define SKV     2048
#define DIM     1024
#define HEADS   16
#define DHEAD   64
#define INNER   1024            // HEADS * DIM_HEAD
#define MQ      (BATCH * SQ)    // 4096
#define MKV     (BATCH * SKV)   // 4096

// Scratch (no cudaMalloc allowed) — all fp16 now
__device__ __half g_qh  [MQ  * INNER];                 // Q (x0.125, fp16)
__device__ __half g_kh  [MKV * INNER];                 // K fp16 [kv][d]
__device__ __half g_vh  [MKV * INNER];                 // V fp16 [kv][d]
__device__ __half g_vt  [BATCH * HEADS * DHEAD * SKV]; // V^T fp16 [(b,h,d)][kv]
__device__ __half g_oh  [MQ  * INNER];                 // attention out fp16
__device__ __half g_xqh [MQ  * DIM];                   // x_q fp16
__device__ __half g_xkvh[MKV * DIM];                   // x_kv fp16
__device__ __half g_wth [3 * INNER * DIM];             // W_qkv^T fp16 [3072][1024]
__device__ __half g_woth[DIM * INNER];                 // W_out^T fp16 [1024][1024]

// warp-level fp16 MMA: D[16x8] += A[16x16] * B[16x8]  (row.col, fp32 accum)
__device__ __forceinline__ void mma_f16(float* d, const uint32_t* a, const uint32_t* b) {
    asm volatile(
        "mma.sync.aligned.m16n8k16.row.col.f32.f16.f16.f32 "
        "{%0,%1,%2,%3}, {%4,%5,%6,%7}, {%8,%9}, {%0,%1,%2,%3};"
        : "+f"(d[0]), "+f"(d[1]), "+f"(d[2]), "+f"(d[3])
        : "r"(a[0]), "r"(a[1]), "r"(a[2]), "r"(a[3]), "r"(b[0]), "r"(b[1]));
}

// async 16B copy gmem -> smem
__device__ __forceinline__ void cp_async16(void* sptr, const void* gptr) {
    uint32_t sa = (uint32_t)__cvta_generic_to_shared(sptr);
    asm volatile("cp.async.cg.shared.global [%0], [%1], 16;" :: "r"(sa), "l"(gptr));
}
#define CP_COMMIT()  asm volatile("cp.async.commit_group;" ::: "memory")
#define CP_WAIT0()   asm volatile("cp.async.wait_group 0;" ::: "memory")

__device__ __forceinline__ uint32_t h2_u32(half2 h) {
    return *(uint32_t*)&h;
}

// ===========================================================================
// prep: fp32 -> fp16 elementwise
// ===========================================================================
__global__ __launch_bounds__(256) void f2h(
    const float* __restrict__ in, __half* __restrict__ out, int n4)
{
    const int i = blockIdx.x * 256 + threadIdx.x;
    if (i < n4) {
        float4 v = ((const float4*)in)[i];
        uint2 u;
        u.x = h2_u32(__floats2half2_rn(v.x, v.y));
        u.y = h2_u32(__floats2half2_rn(v.z, v.w));
        ((uint2*)out)[i] = u;
    }
}

// prep: fp32 [R][C] -> fp16 transposed [C][R]
__global__ void transpose_f2h(
    const float* __restrict__ in, __half* __restrict__ out, int R, int C)
{
    __shared__ float ts[32][33];
    const int bx = blockIdx.x * 32;   // col tile
    const int by = blockIdx.y * 32;   // row tile
    #pragma unroll
    for (int i = 0; i < 32; i += 8)
        ts[threadIdx.y + i][threadIdx.x] =
            in[(size_t)(by + threadIdx.y + i) * C + bx + threadIdx.x];
    __syncthreads();
    #pragma unroll
    for (int i = 0; i < 32; i += 8)
        out[(size_t)(bx + threadIdx.y + i) * R + by + threadIdx.x] =
            __float2half_rn(ts[threadIdx.x][threadIdx.y + i]);
}

// prep: V fp16 [kv][d] -> V^T fp16 [(b,h,d)][kv], 64x64 tiles
__global__ __launch_bounds__(256) void vt_prep(
    const __half* __restrict__ vh, __half* __restrict__ vt)
{
    __shared__ __half ts[64 * 72];
    const int kv0 = blockIdx.x * 64;
    const int h   = blockIdx.y;
    const int b   = blockIdx.z;
    const int tid = threadIdx.x;

    #pragma unroll
    for (int it = 0; it < 2; it++) {
        const int idx = it * 256 + tid;
        const int r = idx >> 3, s8 = (idx & 7) * 8;
        *(uint4*)(ts + r * 72 + s8) =
            *(const uint4*)(vh + ((size_t)b * SKV + kv0 + r) * INNER + h * DHEAD + s8);
    }
    __syncthreads();
    #pragma unroll
    for (int it = 0; it < 2; it++) {
        const int idx = it * 256 + tid;
        const int d = idx >> 3, s8 = (idx & 7) * 8;
        uint4 uv;
        __half* tp = (__half*)&uv;
        #pragma unroll
        for (int m = 0; m < 8; m++) tp[m] = ts[(s8 + m) * 72 + d];
        *(uint4*)(vt + ((size_t)((b * HEADS + h) * DHEAD + d)) * SKV + kv0 + s8) = uv;
    }
}

// ===========================================================================
// fp16 tensor-core GEMM body: C[M,N] = A[M,K] @ Bt[N,K]^T
// Both operands fp16 K-major. CTA tile 128x128, 256 threads (8 warps,
// 2x4 grid of 64x32 warp tiles), K-tile 64 (4 k16 steps), cp.async double
// buffer, ONE sync per chunk, 2 CTAs/SM.
// OUT_HALF=1: write fp16 (x scale); OUT_HALF=0: write fp32 + bias.
// ===========================================================================
#define PH   72                  // smem pitch (halves); frag banks 4g+t
#define P32  36                  // pitch in u32
#define TILE_H (128 * PH)        // 9216 halves per tile
#define SM_HALVES (4 * TILE_H)   // 2 bufs x (A+B)
#define SM_BYTES  (SM_HALVES * 2)   // 73728

template<int OUT_HALF>
__device__ __forceinline__ void gemm_body_h(
    const __half* __restrict__ Ab, const __half* __restrict__ Bb,
    void* __restrict__ Cb, const float* __restrict__ biasp,
    int K, int lda, int ldb, int ldc, float scale, __half* smem)
{
    __half* As[2] = { smem,          smem + 2 * TILE_H };
    __half* Bs[2] = { smem + TILE_H, smem + 3 * TILE_H };

    const int tid  = threadIdx.x;
    const int wid  = tid >> 5;
    const int lane = tid & 31;
    const int g    = lane >> 2;
    const int t    = lane & 3;
    const int wrow = (wid & 1) * 64;
    const int wcol = (wid >> 1) * 32;

    float acc[4][4][4];
    #pragma unroll
    for (int i = 0; i < 4; i++)
        #pragma unroll
        for (int j = 0; j < 4; j++)
            #pragma unroll
            for (int r = 0; r < 4; r++) acc[i][j][r] = 0.f;

    // A tile: 128 rows x 128B; B tile: 128 rows x 128B -> 8 cp16/thread
    auto cp_tile = [&](int k0, int buf) {
        #pragma unroll
        for (int i = 0; i < 4; i++) {
            const int idx = i * 256 + tid;
            const int r = idx >> 3, c8 = (idx & 7) * 8;
            cp_async16(As[buf] + r * PH + c8, Ab + (size_t)r * lda + k0 + c8);
            cp_async16(Bs[buf] + r * PH + c8, Bb + (size_t)r * ldb + k0 + c8);
        }
        CP_COMMIT();
    };

    cp_tile(0, 0);

    const int nch = K >> 6;
    for (int ch = 0; ch < nch; ch++) {
        const int buf = ch & 1;

        CP_WAIT0();
        __syncthreads();

        if (ch + 1 < nch) cp_tile((ch + 1) * 64, buf ^ 1);

        const uint32_t* A32 = (const uint32_t*)As[buf];
        const uint32_t* B32 = (const uint32_t*)Bs[buf];

        #pragma unroll
        for (int ks = 0; ks < 4; ks++) {
            const int k8 = ks * 8;
            uint32_t af[4][4], bf[4][2];
            #pragma unroll
            for (int i = 0; i < 4; i++) {
                const int r0 = wrow + i * 16 + g;
                af[i][0] = A32[(r0    ) * P32 + k8 + t];
                af[i][1] = A32[(r0 + 8) * P32 + k8 + t];
                af[i][2] = A32[(r0    ) * P32 + k8 + t + 4];
                af[i][3] = A32[(r0 + 8) * P32 + k8 + t + 4];
            }
            #pragma unroll
            for (int j = 0; j < 4; j++) {
                const int n = wcol + j * 8 + g;
                bf[j][0] = B32[n * P32 + k8 + t];
                bf[j][1] = B32[n * P32 + k8 + t + 4];
            }
            #pragma unroll
            for (int i = 0; i < 4; i++)
                #pragma unroll
                for (int j = 0; j < 4; j++)
                    mma_f16(acc[i][j], af[i], bf[j]);
        }
    }

    #pragma unroll
    for (int i = 0; i < 4; i++) {
        const int r0 = wrow + i * 16 + g;
        #pragma unroll
        for (int j = 0; j < 4; j++) {
            const int c = wcol + j * 8 + 2 * t;
            if (OUT_HALF) {
                __half* Ch = (__half*)Cb;
                *(half2*)(Ch + (size_t)r0 * ldc + c) =
                    __floats2half2_rn(acc[i][j][0] * scale, acc[i][j][1] * scale);
                *(half2*)(Ch + (size_t)(r0 + 8) * ldc + c) =
                    __floats2half2_rn(acc[i][j][2] * scale, acc[i][j][3] * scale);
            } else {
                float* Cf = (float*)Cb;
                const float b0 = biasp[c], b1 = biasp[c + 1];
                float2 v0 = { acc[i][j][0] + b0, acc[i][j][1] + b1 };
                float2 v1 = { acc[i][j][2] + b0, acc[i][j][3] + b1 };
                *(float2*)(Cf + (size_t)r0 * ldc + c)       = v0;
                *(float2*)(Cf + (size_t)(r0 + 8) * ldc + c) = v1;
            }
        }
    }
}

// Fused QKV projection: grid (24, 32). bx<8 -> Q (x0.125), 8..15 -> K, 16..23 -> V.
__global__ __launch_bounds__(256, 2) void gemm_qkv_h(
    const __half* __restrict__ xqh, const __half* __restrict__ xkvh,
    const __half* __restrict__ wt,
    __half* __restrict__ qh, __half* __restrict__ kh, __half* __restrict__ vh)
{
    extern __shared__ __half smh[];
    const int brow  = blockIdx.y * 128;
    const int bx    = blockIdx.x;
    const int route = bx >> 3;          // 0 Q, 1 K, 2 V
    const int bcol  = (bx & 7) * 128;

    const __half* A = (route == 0) ? xqh : xkvh;
    __half* C = (route == 0) ? qh : (route == 1) ? kh : vh;
    const float scale = (route == 0) ? 0.125f : 1.0f;

    gemm_body_h<1>(A + (size_t)brow * DIM, wt + (size_t)bx * 128 * DIM,
                   C + (size_t)brow * INNER + bcol, nullptr,
                   DIM, DIM, DIM, INNER, scale, smh);
}

// Output projection: out = O @ W_out + b_out (fp32 out)
__global__ __launch_bounds__(256, 2) void gemm_out_h(
    const __half* __restrict__ oh, const __half* __restrict__ wot,
    float* __restrict__ out, const float* __restrict__ bias)
{
    extern __shared__ __half smh[];
    const int brow = blockIdx.y * 128;
    const int bcol = blockIdx.x * 128;
    gemm_body_h<0>(oh + (size_t)brow * INNER, wot + (size_t)bcol * INNER,
                   out + (size_t)brow * DIM + bcol, bias + bcol,
                   INNER, INNER, INNER, DIM, 1.f, smh);
}

// ===========================================================================
// fp16 tensor-core flash attention (m16n8k16).
// CTA: 256 q-rows x (b,h), 512 threads = 16 warps x 16 rows, KV tiles of 32.
// Q pre-scaled fp16 in registers; K fp16 [kv][d]; V^T fp16 [d][kv] so PV
// B-frags are clean u32 loads. P packs from the S C-frag natively (fp16
// k16 A-layout cols 2t,2t+1/2t+8,2t+9 == C-frag pairs). cp.async KV tiles
// (512 cp16 = 1/thread), double buffered, ONE syncthreads per tile.
// ===========================================================================
#define KT     32
#define PHK    72                  // K smem pitch (halves)
#define PHV    40                  // V^T smem pitch (halves)
#define KS_H   (KT * PHK)          // 2304
#define VS_H   (DHEAD * PHV)       // 2560
#define BUF_H  (KS_H + VS_H)       // 4864
#define ATT_SM_BYTES (2 * BUF_H * 2)  // 19456

__global__ __launch_bounds__(512) void attn_h(
    const __half* __restrict__ Qh, const __half* __restrict__ Kh,
    const __half* __restrict__ Vt, __half* __restrict__ Oh)
{
    extern __shared__ __half ash[];

    const int tid  = threadIdx.x;
    const int wid  = tid >> 5;
    const int lane = tid & 31;
    const int g    = lane >> 2;
    const int t    = lane & 3;

    const int qt = blockIdx.x;
    const int h  = blockIdx.y;
    const int b  = blockIdx.z;

    const int qrow0   = qt * 256 + wid * 16 + g;
    const size_t base = ((size_t)b * SQ + qrow0) * INNER + h * DHEAD;

    // Q fragments (fp16, pre-scaled by 0.125 in the projection epilogue)
    uint32_t qa[4][4];
    {
        const uint32_t* q0u = (const uint32_t*)(Qh + base);
        const uint32_t* q1u = (const uint32_t*)(Qh + base + 8 * INNER);
        #pragma unroll
        for (int ks = 0; ks < 4; ks++) {
            qa[ks][0] = q0u[8 * ks + t];
            qa[ks][1] = q1u[8 * ks + t];
            qa[ks][2] = q0u[8 * ks + t + 4];
            qa[ks][3] = q1u[8 * ks + t + 4];
        }
    }

    float m = -INFINITY;
    float l0 = 0.f, l1 = 0.f;
    float o[8][4];
    #pragma unroll
    for (int j = 0; j < 8; j++)
        #pragma unroll
        for (int r = 0; r < 4; r++) o[j][r] = 0.f;

    // tile copy: tid<256 -> K (32 rows x 128B), tid>=256 -> V^T (64 rows x 64B)
    auto cp_tile = [&](int n, int buf) {
        __half* Ks = ash + buf * BUF_H;
        __half* Vs = Ks + KS_H;
        if (tid < 256) {
            const int r = tid >> 3, s8 = (tid & 7) * 8;
            cp_async16(Ks + r * PHK + s8,
                       Kh + ((size_t)b * SKV + n * KT + r) * INNER + h * DHEAD + s8);
        } else {
            const int u = tid - 256;
            const int d = u >> 2, s8 = (u & 3) * 8;
            cp_async16(Vs + d * PHV + s8,
                       Vt + ((size_t)((b * HEADS + h) * DHEAD + d)) * SKV + n * KT + s8);
        }
        CP_COMMIT();
    };

    cp_tile(0, 0);

    const int NT = SKV / KT;   // 64
    for (int n = 0; n < NT; n++) {
        const int buf = n & 1;

        CP_WAIT0();
        __syncthreads();

        if (n + 1 < NT) cp_tile(n + 1, buf ^ 1);

        const uint32_t* K32 = (const uint32_t*)(ash + buf * BUF_H);
        const uint32_t* V32 = (const uint32_t*)(ash + buf * BUF_H + KS_H);

        // ---- S[16x32] = Q @ K^T
        float s[4][4];
        #pragma unroll
        for (int j = 0; j < 4; j++)
            #pragma unroll
            for (int r = 0; r < 4; r++) s[j][r] = 0.f;

        #pragma unroll
        for (int ks = 0; ks < 4; ks++) {
            const int k8 = ks * 8;
            uint32_t bf[4][2];
            #pragma unroll
            for (int j = 0; j < 4; j++) {
                const int nn = j * 8 + g;
                bf[j][0] = K32[nn * (PHK / 2) + k8 + t];
                bf[j][1] = K32[nn * (PHK / 2) + k8 + t + 4];
            }
            #pragma unroll
            for (int j = 0; j < 4; j++)
                mma_f16(s[j], qa[ks], bf[j]);
        }

        // ---- warp-uniform max
        float tm = -INFINITY;
        #pragma unroll
        for (int j = 0; j < 4; j++)
            tm = fmaxf(tm, fmaxf(fmaxf(s[j][0], s[j][1]),
                                 fmaxf(s[j][2], s[j][3])));
        #pragma unroll
        for (int d = 16; d >= 1; d >>= 1)
            tm = fmaxf(tm, __shfl_xor_sync(0xffffffffu, tm, d));

        const float mn = fmaxf(m, tm);
        const float a  = __expf(m - mn);
        if (a < 1.f) {
            l0 *= a; l1 *= a;
            #pragma unroll
            for (int j = 0; j < 8; j++) {
                o[j][0] *= a; o[j][1] *= a; o[j][2] *= a; o[j][3] *= a;
            }
        }
        m = mn;

        // ---- exp in-register (fp32), accumulate row sums
        float rs0 = 0.f, rs1 = 0.f;
        #pragma unroll
        for (int j = 0; j < 4; j++) {
            s[j][0] = __expf(s[j][0] - m);
            s[j][1] = __expf(s[j][1] - m);
            s[j][2] = __expf(s[j][2] - m);
            s[j][3] = __expf(s[j][3] - m);
            rs0 += s[j][0] + s[j][1];
            rs1 += s[j][2] + s[j][3];
        }
        rs0 += __shfl_xor_sync(0xffffffffu, rs0, 1);
        rs0 += __shfl_xor_sync(0xffffffffu, rs0, 2);
        rs1 += __shfl_xor_sync(0xffffffffu, rs1, 1);
        rs1 += __shfl_xor_sync(0xffffffffu, rs1, 2);
        l0 += rs0; l1 += rs1;

        // ---- O[16x64] += P[16x32] @ V[32x64]; P packed from C-frags.
        // fp16 k16 A-layout: a0 = P[g][16k+2t..+1] = s[2k] pair; a2 = s[2k+1].
        #pragma unroll
        for (int ks = 0; ks < 2; ks++) {
            uint32_t pa[4];
            pa[0] = h2_u32(__floats2half2_rn(s[2 * ks    ][0], s[2 * ks    ][1]));
            pa[1] = h2_u32(__floats2half2_rn(s[2 * ks    ][2], s[2 * ks    ][3]));
            pa[2] = h2_u32(__floats2half2_rn(s[2 * ks + 1][0], s[2 * ks + 1][1]));
            pa[3] = h2_u32(__floats2half2_rn(s[2 * ks + 1][2], s[2 * ks + 1][3]));
            const int k8 = ks * 8;
            #pragma unroll
            for (int j = 0; j < 8; j++) {
                uint32_t bf[2];
                const int nn = j * 8 + g;
                bf[0] = V32[nn * (PHV / 2) + k8 + t];
                bf[1] = V32[nn * (PHV / 2) + k8 + t + 4];
                mma_f16(o[j], pa, bf);
            }
        }
    }

    // ---- epilogue: fp16 O (consumed by the output GEMM)
    const float inv0 = 1.f / l0;
    const float inv1 = 1.f / l1;
    __half* o0 = Oh + base;
    __half* o1 = o0 + 8 * INNER;
    #pragma unroll
    for (int j = 0; j < 8; j++) {
        const int c = j * 8 + 2 * t;
        *(half2*)(o0 + c) = __floats2half2_rn(o[j][0] * inv0, o[j][1] * inv0);
        *(half2*)(o1 + c) = __floats2half2_rn(o[j][2] * inv1, o[j][3] * inv1);
    }
}

// ===========================================================================
// kernel_launch
// ===========================================================================
extern "C" void kernel_launch(void* const* d_in, const int* in_sizes, int n_in,
                              void* d_out, int out_size)
{
    const float* x_q   = (const float*)d_in[0];
    const float* x_kv  = (const float*)d_in[1];
    const float* W_qkv = (const float*)d_in[2];  // [1024, 3072]
    const float* W_out = (const float*)d_in[3];  // [1024, 1024]
    const float* b_out = (const float*)d_in[4];  // [1024]
    float* out = (float*)d_out;

    __half *qh, *kh, *vh, *vt, *oh, *xqh, *xkvh, *wth, *woth;
    cudaGetSymbolAddress((void**)&qh,   g_qh);
    cudaGetSymbolAddress((void**)&kh,   g_kh);
    cudaGetSymbolAddress((void**)&vh,   g_vh);
    cudaGetSymbolAddress((void**)&vt,   g_vt);
    cudaGetSymbolAddress((void**)&oh,   g_oh);
    cudaGetSymbolAddress((void**)&xqh,  g_xqh);
    cudaGetSymbolAddress((void**)&xkvh, g_xkvh);
    cudaGetSymbolAddress((void**)&wth,  g_wth);
    cudaGetSymbolAddress((void**)&woth, g_woth);

    cudaFuncSetAttribute(gemm_qkv_h,
                         cudaFuncAttributeMaxDynamicSharedMemorySize, SM_BYTES);
    cudaFuncSetAttribute(gemm_out_h,
                         cudaFuncAttributeMaxDynamicSharedMemorySize, SM_BYTES);
    cudaFuncSetAttribute(attn_h,
                         cudaFuncAttributeMaxDynamicSharedMemorySize, ATT_SM_BYTES);

    // prep: fp16 conversions (+ weight transposes)
    f2h<<<(MQ * DIM / 4 + 255) / 256, 256>>>(x_q,  xqh,  MQ * DIM / 4);
    f2h<<<(MKV * DIM / 4 + 255) / 256, 256>>>(x_kv, xkvh, MKV * DIM / 4);
    transpose_f2h<<<dim3(3 * INNER / 32, DIM / 32), dim3(32, 8)>>>(W_qkv, wth, DIM, 3 * INNER);
    transpose_f2h<<<dim3(DIM / 32, INNER / 32), dim3(32, 8)>>>(W_out, woth, INNER, DIM);

    // [Q*0.125 | K | V] = [x_q | x_kv | x_kv] @ W_qkv  (fp16 out)
    gemm_qkv_h<<<dim3(24, MQ / 128), 256, SM_BYTES>>>(xqh, xkvh, wth, qh, kh, vh);

    // V -> V^T per (b,h)
    vt_prep<<<dim3(SKV / 64, HEADS, BATCH), 256>>>(vh, vt);

    // attention -> O fp16
    attn_h<<<dim3(SQ / 256, HEADS, BATCH), 512, ATT_SM_BYTES>>>(qh, kh, vt, oh);

    // out = O @ W_out + b_out  (fp32 out)
    gemm_out_h<<<dim3(DIM / 128, MQ / 128), 256, SM_BYTES>>>(oh, woth, out, b_out);
}

// round 16
// speedup vs baseline: 2.4901x; 1.6418x over previous
#include <cuda_runtime.h>
#include <cuda_fp16.h>
#include <cstdint>
#include <math.h>

// Problem constants (fixed by the dataset)
#define BATCH   2
#define SQ      2048
#define SKV     2048
#define DIM     1024
#define HEADS   16
#define DHEAD   64
#define INNER   1024            // HEADS * DIM_HEAD
#define MQ      (BATCH * SQ)    // 4096
#define MKV     (BATCH * SKV)   // 4096

// Scratch (no cudaMalloc allowed) — all fp16
__device__ __half g_qh  [MQ  * INNER];                 // Q (x 0.125*log2e, fp16)
__device__ __half g_kh  [MKV * INNER];                 // K fp16 [kv][d]
__device__ __half g_vh  [MKV * INNER];                 // V fp16 [kv][d]
__device__ __half g_vt  [BATCH * HEADS * DHEAD * SKV]; // V^T fp16 [(b,h,d)][kv]
__device__ __half g_oh  [MQ  * INNER];                 // attention out fp16
__device__ __half g_xqh [MQ  * DIM];                   // x_q fp16
__device__ __half g_xkvh[MKV * DIM];                   // x_kv fp16
__device__ __half g_wth [3 * INNER * DIM];             // W_qkv^T fp16 [3072][1024]
__device__ __half g_woth[DIM * INNER];                 // W_out^T fp16 [1024][1024]

// warp-level fp16 MMA: D[16x8] += A[16x16] * B[16x8]  (row.col, fp32 accum)
__device__ __forceinline__ void mma_f16(float* d, const uint32_t* a, const uint32_t* b) {
    asm volatile(
        "mma.sync.aligned.m16n8k16.row.col.f32.f16.f16.f32 "
        "{%0,%1,%2,%3}, {%4,%5,%6,%7}, {%8,%9}, {%0,%1,%2,%3};"
        : "+f"(d[0]), "+f"(d[1]), "+f"(d[2]), "+f"(d[3])
        : "r"(a[0]), "r"(a[1]), "r"(a[2]), "r"(a[3]), "r"(b[0]), "r"(b[1]));
}

// async 16B copy gmem -> smem
__device__ __forceinline__ void cp_async16(void* sptr, const void* gptr) {
    uint32_t sa = (uint32_t)__cvta_generic_to_shared(sptr);
    asm volatile("cp.async.cg.shared.global [%0], [%1], 16;" :: "r"(sa), "l"(gptr));
}
#define CP_COMMIT()  asm volatile("cp.async.commit_group;" ::: "memory")
#define CP_WAIT0()   asm volatile("cp.async.wait_group 0;" ::: "memory")

__device__ __forceinline__ uint32_t h2_u32(half2 h) {
    return *(uint32_t*)&h;
}

// bare exp2 (MUFU.EX2) — scores are kept in the log2 domain
__device__ __forceinline__ float ex2f(float x) {
    float r;
    asm("ex2.approx.f32 %0, %1;" : "=f"(r) : "f"(x));
    return r;
}

// ===========================================================================
// prep kernels (unchanged from round 15)
// ===========================================================================
__global__ __launch_bounds__(256) void f2h(
    const float* __restrict__ in, __half* __restrict__ out, int n4)
{
    const int i = blockIdx.x * 256 + threadIdx.x;
    if (i < n4) {
        float4 v = ((const float4*)in)[i];
        uint2 u;
        u.x = h2_u32(__floats2half2_rn(v.x, v.y));
        u.y = h2_u32(__floats2half2_rn(v.z, v.w));
        ((uint2*)out)[i] = u;
    }
}

__global__ void transpose_f2h(
    const float* __restrict__ in, __half* __restrict__ out, int R, int C)
{
    __shared__ float ts[32][33];
    const int bx = blockIdx.x * 32;
    const int by = blockIdx.y * 32;
    #pragma unroll
    for (int i = 0; i < 32; i += 8)
        ts[threadIdx.y + i][threadIdx.x] =
            in[(size_t)(by + threadIdx.y + i) * C + bx + threadIdx.x];
    __syncthreads();
    #pragma unroll
    for (int i = 0; i < 32; i += 8)
        out[(size_t)(bx + threadIdx.y + i) * R + by + threadIdx.x] =
            __float2half_rn(ts[threadIdx.x][threadIdx.y + i]);
}

__global__ __launch_bounds__(256) void vt_prep(
    const __half* __restrict__ vh, __half* __restrict__ vt)
{
    __shared__ __half ts[64 * 72];
    const int kv0 = blockIdx.x * 64;
    const int h   = blockIdx.y;
    const int b   = blockIdx.z;
    const int tid = threadIdx.x;

    #pragma unroll
    for (int it = 0; it < 2; it++) {
        const int idx = it * 256 + tid;
        const int r = idx >> 3, s8 = (idx & 7) * 8;
        *(uint4*)(ts + r * 72 + s8) =
            *(const uint4*)(vh + ((size_t)b * SKV + kv0 + r) * INNER + h * DHEAD + s8);
    }
    __syncthreads();
    #pragma unroll
    for (int it = 0; it < 2; it++) {
        const int idx = it * 256 + tid;
        const int d = idx >> 3, s8 = (idx & 7) * 8;
        uint4 uv;
        __half* tp = (__half*)&uv;
        #pragma unroll
        for (int m = 0; m < 8; m++) tp[m] = ts[(s8 + m) * 72 + d];
        *(uint4*)(vt + ((size_t)((b * HEADS + h) * DHEAD + d)) * SKV + kv0 + s8) = uv;
    }
}

// ===========================================================================
// fp16 GEMM body (unchanged from round 15 — proven)
// ===========================================================================
#define PH   72
#define P32  36
#define TILE_H (128 * PH)
#define SM_HALVES (4 * TILE_H)
#define SM_BYTES  (SM_HALVES * 2)   // 73728

template<int OUT_HALF>
__device__ __forceinline__ void gemm_body_h(
    const __half* __restrict__ Ab, const __half* __restrict__ Bb,
    void* __restrict__ Cb, const float* __restrict__ biasp,
    int K, int lda, int ldb, int ldc, float scale, __half* smem)
{
    __half* As[2] = { smem,          smem + 2 * TILE_H };
    __half* Bs[2] = { smem + TILE_H, smem + 3 * TILE_H };

    const int tid  = threadIdx.x;
    const int wid  = tid >> 5;
    const int lane = tid & 31;
    const int g    = lane >> 2;
    const int t    = lane & 3;
    const int wrow = (wid & 1) * 64;
    const int wcol = (wid >> 1) * 32;

    float acc[4][4][4];
    #pragma unroll
    for (int i = 0; i < 4; i++)
        #pragma unroll
        for (int j = 0; j < 4; j++)
            #pragma unroll
            for (int r = 0; r < 4; r++) acc[i][j][r] = 0.f;

    auto cp_tile = [&](int k0, int buf) {
        #pragma unroll
        for (int i = 0; i < 4; i++) {
            const int idx = i * 256 + tid;
            const int r = idx >> 3, c8 = (idx & 7) * 8;
            cp_async16(As[buf] + r * PH + c8, Ab + (size_t)r * lda + k0 + c8);
            cp_async16(Bs[buf] + r * PH + c8, Bb + (size_t)r * ldb + k0 + c8);
        }
        CP_COMMIT();
    };

    cp_tile(0, 0);

    const int nch = K >> 6;
    for (int ch = 0; ch < nch; ch++) {
        const int buf = ch & 1;

        CP_WAIT0();
        __syncthreads();

        if (ch + 1 < nch) cp_tile((ch + 1) * 64, buf ^ 1);

        const uint32_t* A32 = (const uint32_t*)As[buf];
        const uint32_t* B32 = (const uint32_t*)Bs[buf];

        #pragma unroll
        for (int ks = 0; ks < 4; ks++) {
            const int k8 = ks * 8;
            uint32_t af[4][4], bf[4][2];
            #pragma unroll
            for (int i = 0; i < 4; i++) {
                const int r0 = wrow + i * 16 + g;
                af[i][0] = A32[(r0    ) * P32 + k8 + t];
                af[i][1] = A32[(r0 + 8) * P32 + k8 + t];
                af[i][2] = A32[(r0    ) * P32 + k8 + t + 4];
                af[i][3] = A32[(r0 + 8) * P32 + k8 + t + 4];
            }
            #pragma unroll
            for (int j = 0; j < 4; j++) {
                const int n = wcol + j * 8 + g;
                bf[j][0] = B32[n * P32 + k8 + t];
                bf[j][1] = B32[n * P32 + k8 + t + 4];
            }
            #pragma unroll
            for (int i = 0; i < 4; i++)
                #pragma unroll
                for (int j = 0; j < 4; j++)
                    mma_f16(acc[i][j], af[i], bf[j]);
        }
    }

    #pragma unroll
    for (int i = 0; i < 4; i++) {
        const int r0 = wrow + i * 16 + g;
        #pragma unroll
        for (int j = 0; j < 4; j++) {
            const int c = wcol + j * 8 + 2 * t;
            if (OUT_HALF) {
                __half* Ch = (__half*)Cb;
                *(half2*)(Ch + (size_t)r0 * ldc + c) =
                    __floats2half2_rn(acc[i][j][0] * scale, acc[i][j][1] * scale);
                *(half2*)(Ch + (size_t)(r0 + 8) * ldc + c) =
                    __floats2half2_rn(acc[i][j][2] * scale, acc[i][j][3] * scale);
            } else {
                float* Cf = (float*)Cb;
                const float b0 = biasp[c], b1 = biasp[c + 1];
                float2 v0 = { acc[i][j][0] + b0, acc[i][j][1] + b1 };
                float2 v1 = { acc[i][j][2] + b0, acc[i][j][3] + b1 };
                *(float2*)(Cf + (size_t)r0 * ldc + c)       = v0;
                *(float2*)(Cf + (size_t)(r0 + 8) * ldc + c) = v1;
            }
        }
    }
}

// Q scale: 0.125 (dhead^-0.5) * log2(e) — scores land in the exp2 domain
#define QSCALE 0.180336880111120419f

__global__ __launch_bounds__(256, 2) void gemm_qkv_h(
    const __half* __restrict__ xqh, const __half* __restrict__ xkvh,
    const __half* __restrict__ wt,
    __half* __restrict__ qh, __half* __restrict__ kh, __half* __restrict__ vh)
{
    extern __shared__ __half smh[];
    const int brow  = blockIdx.y * 128;
    const int bx    = blockIdx.x;
    const int route = bx >> 3;          // 0 Q, 1 K, 2 V
    const int bcol  = (bx & 7) * 128;

    const __half* A = (route == 0) ? xqh : xkvh;
    __half* C = (route == 0) ? qh : (route == 1) ? kh : vh;
    const float scale = (route == 0) ? QSCALE : 1.0f;

    gemm_body_h<1>(A + (size_t)brow * DIM, wt + (size_t)bx * 128 * DIM,
                   C + (size_t)brow * INNER + bcol, nullptr,
                   DIM, DIM, DIM, INNER, scale, smh);
}

__global__ __launch_bounds__(256, 2) void gemm_out_h(
    const __half* __restrict__ oh, const __half* __restrict__ wot,
    float* __restrict__ out, const float* __restrict__ bias)
{
    extern __shared__ __half smh[];
    const int brow = blockIdx.y * 128;
    const int bcol = blockIdx.x * 128;
    gemm_body_h<0>(oh + (size_t)brow * INNER, wot + (size_t)bcol * INNER,
                   out + (size_t)brow * DIM + bcol, bias + bcol,
                   INNER, INNER, INNER, DIM, 1.f, smh);
}

// ===========================================================================
// fp16 flash attention v2: CTA = 128 q-rows (256 threads, 8 warps x 16 rows),
// 2 CTAs/SM (barrier decoupling), KV tiles of 64 (halved per-tile overhead),
// exp2-domain softmax (bare MUFU.EX2), P packed from C-frags (no smem).
// ===========================================================================
#define KT     64
#define PHK    72                   // K smem pitch (halves)
#define PHV    72                   // V^T smem pitch (halves)
#define KS_H   (KT * PHK)           // 4608
#define VS_H   (DHEAD * PHV)        // 4608
#define BUF_H  (KS_H + VS_H)        // 9216
#define ATT_SM_BYTES (2 * BUF_H * 2)   // 36864

__global__ __launch_bounds__(256, 2) void attn_h(
    const __half* __restrict__ Qh, const __half* __restrict__ Kh,
    const __half* __restrict__ Vt, __half* __restrict__ Oh)
{
    extern __shared__ __half ash[];

    const int tid  = threadIdx.x;
    const int wid  = tid >> 5;      // 0..7
    const int lane = tid & 31;
    const int g    = lane >> 2;
    const int t    = lane & 3;

    const int qt = blockIdx.x;      // 128-row q tile
    const int h  = blockIdx.y;
    const int b  = blockIdx.z;

    const int qrow0   = qt * 128 + wid * 16 + g;
    const size_t base = ((size_t)b * SQ + qrow0) * INNER + h * DHEAD;

    // Q fragments (fp16, pre-scaled by 0.125*log2e in the projection epilogue)
    uint32_t qa[4][4];
    {
        const uint32_t* q0u = (const uint32_t*)(Qh + base);
        const uint32_t* q1u = (const uint32_t*)(Qh + base + 8 * INNER);
        #pragma unroll
        for (int ks = 0; ks < 4; ks++) {
            qa[ks][0] = q0u[8 * ks + t];
            qa[ks][1] = q1u[8 * ks + t];
            qa[ks][2] = q0u[8 * ks + t + 4];
            qa[ks][3] = q1u[8 * ks + t + 4];
        }
    }

    float m = -INFINITY;            // warp-uniform running max (log2 domain)
    float l0 = 0.f, l1 = 0.f;
    float o[8][4];
    #pragma unroll
    for (int j = 0; j < 8; j++)
        #pragma unroll
        for (int r = 0; r < 4; r++) o[j][r] = 0.f;

    // tile copy: K 64 rows x 128B (512 cp16) + V^T 64 rows x 128B (512 cp16)
    // = 4 cp16 per thread
    auto cp_tile = [&](int n, int buf) {
        __half* Ks = ash + buf * BUF_H;
        __half* Vs = Ks + KS_H;
        #pragma unroll
        for (int it = 0; it < 2; it++) {
            const int idx = it * 256 + tid;
            const int r = idx >> 3, s8 = (idx & 7) * 8;
            cp_async16(Ks + r * PHK + s8,
                       Kh + ((size_t)b * SKV + n * KT + r) * INNER + h * DHEAD + s8);
            cp_async16(Vs + r * PHV + s8,
                       Vt + ((size_t)((b * HEADS + h) * DHEAD + r)) * SKV + n * KT + s8);
        }
        CP_COMMIT();
    };

    cp_tile(0, 0);

    const int NT = SKV / KT;   // 32
    for (int n = 0; n < NT; n++) {
        const int buf = n & 1;

        CP_WAIT0();
        __syncthreads();

        if (n + 1 < NT) cp_tile(n + 1, buf ^ 1);

        const uint32_t* K32 = (const uint32_t*)(ash + buf * BUF_H);
        const uint32_t* V32 = (const uint32_t*)(ash + buf * BUF_H + KS_H);

        // ---- S[16x64] = Q @ K^T  (log2 domain)
        float s[8][4];
        #pragma unroll
        for (int j = 0; j < 8; j++)
            #pragma unroll
            for (int r = 0; r < 4; r++) s[j][r] = 0.f;

        #pragma unroll
        for (int ks = 0; ks < 4; ks++) {
            const int k8 = ks * 8;
            #pragma unroll
            for (int j = 0; j < 8; j++) {
                uint32_t bf[2];
                const int nn = j * 8 + g;
                bf[0] = K32[nn * (PHK / 2) + k8 + t];
                bf[1] = K32[nn * (PHK / 2) + k8 + t + 4];
                mma_f16(s[j], qa[ks], bf);
            }
        }

        // ---- warp-uniform max
        float tm = -INFINITY;
        #pragma unroll
        for (int j = 0; j < 8; j++)
            tm = fmaxf(tm, fmaxf(fmaxf(s[j][0], s[j][1]),
                                 fmaxf(s[j][2], s[j][3])));
        #pragma unroll
        for (int d = 16; d >= 1; d >>= 1)
            tm = fmaxf(tm, __shfl_xor_sync(0xffffffffu, tm, d));

        const float mn = fmaxf(m, tm);
        const float a  = ex2f(m - mn);
        if (a < 1.f) {
            l0 *= a; l1 *= a;
            #pragma unroll
            for (int j = 0; j < 8; j++) {
                o[j][0] *= a; o[j][1] *= a; o[j][2] *= a; o[j][3] *= a;
            }
        }
        m = mn;

        // ---- exp2 in-register, accumulate row sums
        float rs0 = 0.f, rs1 = 0.f;
        #pragma unroll
        for (int j = 0; j < 8; j++) {
            s[j][0] = ex2f(s[j][0] - m);
            s[j][1] = ex2f(s[j][1] - m);
            s[j][2] = ex2f(s[j][2] - m);
            s[j][3] = ex2f(s[j][3] - m);
            rs0 += s[j][0] + s[j][1];
            rs1 += s[j][2] + s[j][3];
        }
        rs0 += __shfl_xor_sync(0xffffffffu, rs0, 1);
        rs0 += __shfl_xor_sync(0xffffffffu, rs0, 2);
        rs1 += __shfl_xor_sync(0xffffffffu, rs1, 1);
        rs1 += __shfl_xor_sync(0xffffffffu, rs1, 2);
        l0 += rs0; l1 += rs1;

        // ---- O[16x64] += P[16x64] @ V[64x64], P packed from C-frags
        #pragma unroll
        for (int ks = 0; ks < 4; ks++) {
            uint32_t pa[4];
            pa[0] = h2_u32(__floats2half2_rn(s[2 * ks    ][0], s[2 * ks    ][1]));
            pa[1] = h2_u32(__floats2half2_rn(s[2 * ks    ][2], s[2 * ks    ][3]));
            pa[2] = h2_u32(__floats2half2_rn(s[2 * ks + 1][0], s[2 * ks + 1][1]));
            pa[3] = h2_u32(__floats2half2_rn(s[2 * ks + 1][2], s[2 * ks + 1][3]));
            const int k8 = ks * 8;
            #pragma unroll
            for (int j = 0; j < 8; j++) {
                uint32_t bf[2];
                const int nn = j * 8 + g;
                bf[0] = V32[nn * (PHV / 2) + k8 + t];
                bf[1] = V32[nn * (PHV / 2) + k8 + t + 4];
                mma_f16(o[j], pa, bf);
            }
        }
    }

    // ---- epilogue: fp16 O
    const float inv0 = 1.f / l0;
    const float inv1 = 1.f / l1;
    __half* o0 = Oh + base;
    __half* o1 = o0 + 8 * INNER;
    #pragma unroll
    for (int j = 0; j < 8; j++) {
        const int c = j * 8 + 2 * t;
        *(half2*)(o0 + c) = __floats2half2_rn(o[j][0] * inv0, o[j][1] * inv0);
        *(half2*)(o1 + c) = __floats2half2_rn(o[j][2] * inv1, o[j][3] * inv1);
    }
}

// ===========================================================================
// kernel_launch
// ===========================================================================
extern "C" void kernel_launch(void* const* d_in, const int* in_sizes, int n_in,
                              void* d_out, int out_size)
{
    const float* x_q   = (const float*)d_in[0];
    const float* x_kv  = (const float*)d_in[1];
    const float* W_qkv = (const float*)d_in[2];  // [1024, 3072]
    const float* W_out = (const float*)d_in[3];  // [1024, 1024]
    const float* b_out = (const float*)d_in[4];  // [1024]
    float* out = (float*)d_out;

    __half *qh, *kh, *vh, *vt, *oh, *xqh, *xkvh, *wth, *woth;
    cudaGetSymbolAddress((void**)&qh,   g_qh);
    cudaGetSymbolAddress((void**)&kh,   g_kh);
    cudaGetSymbolAddress((void**)&vh,   g_vh);
    cudaGetSymbolAddress((void**)&vt,   g_vt);
    cudaGetSymbolAddress((void**)&oh,   g_oh);
    cudaGetSymbolAddress((void**)&xqh,  g_xqh);
    cudaGetSymbolAddress((void**)&xkvh, g_xkvh);
    cudaGetSymbolAddress((void**)&wth,  g_wth);
    cudaGetSymbolAddress((void**)&woth, g_woth);

    cudaFuncSetAttribute(gemm_qkv_h,
                         cudaFuncAttributeMaxDynamicSharedMemorySize, SM_BYTES);
    cudaFuncSetAttribute(gemm_out_h,
                         cudaFuncAttributeMaxDynamicSharedMemorySize, SM_BYTES);
    cudaFuncSetAttribute(attn_h,
                         cudaFuncAttributeMaxDynamicSharedMemorySize, ATT_SM_BYTES);

    // prep: fp16 conversions (+ weight transposes)
    f2h<<<(MQ * DIM / 4 + 255) / 256, 256>>>(x_q,  xqh,  MQ * DIM / 4);
    f2h<<<(MKV * DIM / 4 + 255) / 256, 256>>>(x_kv, xkvh, MKV * DIM / 4);
    transpose_f2h<<<dim3(3 * INNER / 32, DIM / 32), dim3(32, 8)>>>(W_qkv, wth, DIM, 3 * INNER);
    transpose_f2h<<<dim3(DIM / 32, INNER / 32), dim3(32, 8)>>>(W_out, woth, INNER, DIM);

    // [Q*0.125*log2e | K | V] = [x_q | x_kv | x_kv] @ W_qkv  (fp16 out)
    gemm_qkv_h<<<dim3(24, MQ / 128), 256, SM_BYTES>>>(xqh, xkvh, wth, qh, kh, vh);

    // V -> V^T per (b,h)
    vt_prep<<<dim3(SKV / 64, HEADS, BATCH), 256>>>(vh, vt);

    // attention -> O fp16
    attn_h<<<dim3(SQ / 128, HEADS, BATCH), 256, ATT_SM_BYTES>>>(qh, kh, vt, oh);

    // out = O @ W_out + b_out  (fp32 out)
    gemm_out_h<<<dim3(DIM / 128, MQ / 128), 256, SM_BYTES>>>(oh, woth, out, b_out);
}

// round 17
// speedup vs baseline: 2.5713x; 1.0326x over previous
#include <cuda_runtime.h>
#include <cuda_fp16.h>
#include <cstdint>
#include <math.h>

// Problem constants (fixed by the dataset)
#define BATCH   2
#define SQ      2048
#define SKV     2048
#define DIM     1024
#define HEADS   16
#define DHEAD   64
#define INNER   1024            // HEADS * DIM_HEAD
#define MQ      (BATCH * SQ)    // 4096
#define MKV     (BATCH * SKV)   // 4096

// Scratch (no cudaMalloc allowed) — all fp16
__device__ __half g_qh  [MQ  * INNER];                 // Q (x 0.125*log2e, fp16)
__device__ __half g_kh  [MKV * INNER];                 // K fp16 [kv][d]
__device__ __half g_vh  [MKV * INNER];                 // V fp16 [kv][d]
__device__ __half g_vt  [BATCH * HEADS * DHEAD * SKV]; // V^T fp16 [(b,h,d)][kv]
__device__ __half g_oh  [MQ  * INNER];                 // attention out fp16
__device__ __half g_xqh [MQ  * DIM];                   // x_q fp16
__device__ __half g_xkvh[MKV * DIM];                   // x_kv fp16
__device__ __half g_wth [3 * INNER * DIM];             // W_qkv^T fp16 [3072][1024]
__device__ __half g_woth[DIM * INNER];                 // W_out^T fp16 [1024][1024]

// warp-level fp16 MMA: D[16x8] += A[16x16] * B[16x8]  (row.col, fp32 accum)
__device__ __forceinline__ void mma_f16(float* d, const uint32_t* a, const uint32_t* b) {
    asm volatile(
        "mma.sync.aligned.m16n8k16.row.col.f32.f16.f16.f32 "
        "{%0,%1,%2,%3}, {%4,%5,%6,%7}, {%8,%9}, {%0,%1,%2,%3};"
        : "+f"(d[0]), "+f"(d[1]), "+f"(d[2]), "+f"(d[3])
        : "r"(a[0]), "r"(a[1]), "r"(a[2]), "r"(a[3]), "r"(b[0]), "r"(b[1]));
}

// async 16B copy gmem -> smem
__device__ __forceinline__ void cp_async16(void* sptr, const void* gptr) {
    uint32_t sa = (uint32_t)__cvta_generic_to_shared(sptr);
    asm volatile("cp.async.cg.shared.global [%0], [%1], 16;" :: "r"(sa), "l"(gptr));
}
#define CP_COMMIT()  asm volatile("cp.async.commit_group;" ::: "memory")
#define CP_WAIT0()   asm volatile("cp.async.wait_group 0;" ::: "memory")
#define CP_WAIT1()   asm volatile("cp.async.wait_group 1;" ::: "memory")

__device__ __forceinline__ uint32_t h2_u32(half2 h) {
    return *(uint32_t*)&h;
}

// bare exp2 (MUFU.EX2) — scores are kept in the log2 domain
__device__ __forceinline__ float ex2f(float x) {
    float r;
    asm("ex2.approx.f32 %0, %1;" : "=f"(r) : "f"(x));
    return r;
}

// ===========================================================================
// prep: fused fp32->fp16 for x_q then x_kv (one launch)
// ===========================================================================
__global__ __launch_bounds__(256) void f2h_all(
    const float* __restrict__ xq, const float* __restrict__ xkv,
    __half* __restrict__ xqh, __half* __restrict__ xkvh, int n4q, int n4kv)
{
    int i = blockIdx.x * 256 + threadIdx.x;
    const float* in; __half* out;
    if (i < n4q) { in = xq; out = xqh; }
    else         { i -= n4q; if (i >= n4kv) return; in = xkv; out = xkvh; }
    float4 v = ((const float4*)in)[i];
    uint2 u;
    u.x = h2_u32(__floats2half2_rn(v.x, v.y));
    u.y = h2_u32(__floats2half2_rn(v.z, v.w));
    ((uint2*)out)[i] = u;
}

// prep: fused transpose+f2h for both weight matrices (route by blockIdx.x)
// W_qkv [1024,3072] -> [3072,1024] uses bx 0..95; W_out [1024,1024] -> bx 96..127
__global__ void transpose_f2h_all(
    const float* __restrict__ wqkv, const float* __restrict__ wout,
    __half* __restrict__ wth, __half* __restrict__ woth)
{
    __shared__ float ts[32][33];
    int bxg = blockIdx.x;
    const float* in; __half* out; int R = 1024, C; int bx;
    if (bxg < 96) { in = wqkv; out = wth;  C = 3072; bx = bxg * 32; }
    else          { in = wout; out = woth; C = 1024; bx = (bxg - 96) * 32; }
    const int by = blockIdx.y * 32;
    #pragma unroll
    for (int i = 0; i < 32; i += 8)
        ts[threadIdx.y + i][threadIdx.x] =
            in[(size_t)(by + threadIdx.y + i) * C + bx + threadIdx.x];
    __syncthreads();
    #pragma unroll
    for (int i = 0; i < 32; i += 8)
        out[(size_t)(bx + threadIdx.y + i) * R + by + threadIdx.x] =
            __float2half_rn(ts[threadIdx.x][threadIdx.y + i]);
}

__global__ __launch_bounds__(256) void vt_prep(
    const __half* __restrict__ vh, __half* __restrict__ vt)
{
    __shared__ __half ts[64 * 72];
    const int kv0 = blockIdx.x * 64;
    const int h   = blockIdx.y;
    const int b   = blockIdx.z;
    const int tid = threadIdx.x;

    #pragma unroll
    for (int it = 0; it < 2; it++) {
        const int idx = it * 256 + tid;
        const int r = idx >> 3, s8 = (idx & 7) * 8;
        *(uint4*)(ts + r * 72 + s8) =
            *(const uint4*)(vh + ((size_t)b * SKV + kv0 + r) * INNER + h * DHEAD + s8);
    }
    __syncthreads();
    #pragma unroll
    for (int it = 0; it < 2; it++) {
        const int idx = it * 256 + tid;
        const int d = idx >> 3, s8 = (idx & 7) * 8;
        uint4 uv;
        __half* tp = (__half*)&uv;
        #pragma unroll
        for (int m = 0; m < 8; m++) tp[m] = ts[(s8 + m) * 72 + d];
        *(uint4*)(vt + ((size_t)((b * HEADS + h) * DHEAD + d)) * SKV + kv0 + s8) = uv;
    }
}

// ===========================================================================
// fp16 GEMM body (frozen since round 15 — proven)
// ===========================================================================
#define PH   72
#define P32  36
#define TILE_H (128 * PH)
#define SM_HALVES (4 * TILE_H)
#define SM_BYTES  (SM_HALVES * 2)   // 73728

template<int OUT_HALF>
__device__ __forceinline__ void gemm_body_h(
    const __half* __restrict__ Ab, const __half* __restrict__ Bb,
    void* __restrict__ Cb, const float* __restrict__ biasp,
    int K, int lda, int ldb, int ldc, float scale, __half* smem)
{
    __half* As[2] = { smem,          smem + 2 * TILE_H };
    __half* Bs[2] = { smem + TILE_H, smem + 3 * TILE_H };

    const int tid  = threadIdx.x;
    const int wid  = tid >> 5;
    const int lane = tid & 31;
    const int g    = lane >> 2;
    const int t    = lane & 3;
    const int wrow = (wid & 1) * 64;
    const int wcol = (wid >> 1) * 32;

    float acc[4][4][4];
    #pragma unroll
    for (int i = 0; i < 4; i++)
        #pragma unroll
        for (int j = 0; j < 4; j++)
            #pragma unroll
            for (int r = 0; r < 4; r++) acc[i][j][r] = 0.f;

    auto cp_tile = [&](int k0, int buf) {
        #pragma unroll
        for (int i = 0; i < 4; i++) {
            const int idx = i * 256 + tid;
            const int r = idx >> 3, c8 = (idx & 7) * 8;
            cp_async16(As[buf] + r * PH + c8, Ab + (size_t)r * lda + k0 + c8);
            cp_async16(Bs[buf] + r * PH + c8, Bb + (size_t)r * ldb + k0 + c8);
        }
        CP_COMMIT();
    };

    cp_tile(0, 0);

    const int nch = K >> 6;
    for (int ch = 0; ch < nch; ch++) {
        const int buf = ch & 1;

        CP_WAIT0();
        __syncthreads();

        if (ch + 1 < nch) cp_tile((ch + 1) * 64, buf ^ 1);

        const uint32_t* A32 = (const uint32_t*)As[buf];
        const uint32_t* B32 = (const uint32_t*)Bs[buf];

        #pragma unroll
        for (int ks = 0; ks < 4; ks++) {
            const int k8 = ks * 8;
            uint32_t af[4][4], bf[4][2];
            #pragma unroll
            for (int i = 0; i < 4; i++) {
                const int r0 = wrow + i * 16 + g;
                af[i][0] = A32[(r0    ) * P32 + k8 + t];
                af[i][1] = A32[(r0 + 8) * P32 + k8 + t];
                af[i][2] = A32[(r0    ) * P32 + k8 + t + 4];
                af[i][3] = A32[(r0 + 8) * P32 + k8 + t + 4];
            }
            #pragma unroll
            for (int j = 0; j < 4; j++) {
                const int n = wcol + j * 8 + g;
                bf[j][0] = B32[n * P32 + k8 + t];
                bf[j][1] = B32[n * P32 + k8 + t + 4];
            }
            #pragma unroll
            for (int i = 0; i < 4; i++)
                #pragma unroll
                for (int j = 0; j < 4; j++)
                    mma_f16(acc[i][j], af[i], bf[j]);
        }
    }

    #pragma unroll
    for (int i = 0; i < 4; i++) {
        const int r0 = wrow + i * 16 + g;
        #pragma unroll
        for (int j = 0; j < 4; j++) {
            const int c = wcol + j * 8 + 2 * t;
            if (OUT_HALF) {
                __half* Ch = (__half*)Cb;
                *(half2*)(Ch + (size_t)r0 * ldc + c) =
                    __floats2half2_rn(acc[i][j][0] * scale, acc[i][j][1] * scale);
                *(half2*)(Ch + (size_t)(r0 + 8) * ldc + c) =
                    __floats2half2_rn(acc[i][j][2] * scale, acc[i][j][3] * scale);
            } else {
                float* Cf = (float*)Cb;
                const float b0 = biasp[c], b1 = biasp[c + 1];
                float2 v0 = { acc[i][j][0] + b0, acc[i][j][1] + b1 };
                float2 v1 = { acc[i][j][2] + b0, acc[i][j][3] + b1 };
                *(float2*)(Cf + (size_t)r0 * ldc + c)       = v0;
                *(float2*)(Cf + (size_t)(r0 + 8) * ldc + c) = v1;
            }
        }
    }
}

// Q scale: 0.125 (dhead^-0.5) * log2(e) — scores land in the exp2 domain
#define QSCALE 0.180336880111120419f

__global__ __launch_bounds__(256, 2) void gemm_qkv_h(
    const __half* __restrict__ xqh, const __half* __restrict__ xkvh,
    const __half* __restrict__ wt,
    __half* __restrict__ qh, __half* __restrict__ kh, __half* __restrict__ vh)
{
    extern __shared__ __half smh[];
    const int brow  = blockIdx.y * 128;
    const int bx    = blockIdx.x;
    const int route = bx >> 3;          // 0 Q, 1 K, 2 V
    const int bcol  = (bx & 7) * 128;

    const __half* A = (route == 0) ? xqh : xkvh;
    __half* C = (route == 0) ? qh : (route == 1) ? kh : vh;
    const float scale = (route == 0) ? QSCALE : 1.0f;

    gemm_body_h<1>(A + (size_t)brow * DIM, wt + (size_t)bx * 128 * DIM,
                   C + (size_t)brow * INNER + bcol, nullptr,
                   DIM, DIM, DIM, INNER, scale, smh);
}

__global__ __launch_bounds__(256, 2) void gemm_out_h(
    const __half* __restrict__ oh, const __half* __restrict__ wot,
    float* __restrict__ out, const float* __restrict__ bias)
{
    extern __shared__ __half smh[];
    const int brow = blockIdx.y * 128;
    const int bcol = blockIdx.x * 128;
    gemm_body_h<0>(oh + (size_t)brow * INNER, wot + (size_t)bcol * INNER,
                   out + (size_t)brow * DIM + bcol, bias + bcol,
                   INNER, INNER, INNER, DIM, 1.f, smh);
}

// ===========================================================================
// fp16 flash attention v3: CTA = 128 q-rows (256 threads, 8 warps x 16 rows),
// 2 CTAs/SM, KV tiles of 64, THREE-stage cp.async pipeline, exp2 softmax,
// P packed from C-frags, row sums l computed by an extra ones-MMA (fp32
// C-frag accumulator, rescaled online like O).
// ===========================================================================
#define KT     64
#define PHK    72                   // K smem pitch (halves)
#define PHV    72                   // V^T smem pitch (halves)
#define KS_H   (KT * PHK)           // 4608
#define VS_H   (DHEAD * PHV)        // 4608
#define BUF_H  (KS_H + VS_H)        // 9216
#define ATT_SM_BYTES (3 * BUF_H * 2)   // 55296 (3-stage)

#define ONES2  0x3C003C00u          // half2 {1.0, 1.0}

__global__ __launch_bounds__(256, 2) void attn_h(
    const __half* __restrict__ Qh, const __half* __restrict__ Kh,
    const __half* __restrict__ Vt, __half* __restrict__ Oh)
{
    extern __shared__ __half ash[];

    const int tid  = threadIdx.x;
    const int wid  = tid >> 5;      // 0..7
    const int lane = tid & 31;
    const int g    = lane >> 2;
    const int t    = lane & 3;

    const int qt = blockIdx.x;      // 128-row q tile
    const int h  = blockIdx.y;
    const int b  = blockIdx.z;

    const int qrow0   = qt * 128 + wid * 16 + g;
    const size_t base = ((size_t)b * SQ + qrow0) * INNER + h * DHEAD;

    // Q fragments (fp16, pre-scaled by 0.125*log2e in the projection epilogue)
    uint32_t qa[4][4];
    {
        const uint32_t* q0u = (const uint32_t*)(Qh + base);
        const uint32_t* q1u = (const uint32_t*)(Qh + base + 8 * INNER);
        #pragma unroll
        for (int ks = 0; ks < 4; ks++) {
            qa[ks][0] = q0u[8 * ks + t];
            qa[ks][1] = q1u[8 * ks + t];
            qa[ks][2] = q0u[8 * ks + t + 4];
            qa[ks][3] = q1u[8 * ks + t + 4];
        }
    }

    float m = -INFINITY;            // warp-uniform running max (log2 domain)
    float ol[4] = {0.f, 0.f, 0.f, 0.f};   // row-sum accumulator (ones-MMA)
    float o[8][4];
    #pragma unroll
    for (int j = 0; j < 8; j++)
        #pragma unroll
        for (int r = 0; r < 4; r++) o[j][r] = 0.f;

    // tile copy: K 64 rows x 128B + V^T 64 rows x 128B = 4 cp16/thread
    auto cp_tile = [&](int n, int buf) {
        __half* Ks = ash + buf * BUF_H;
        __half* Vs = Ks + KS_H;
        #pragma unroll
        for (int it = 0; it < 2; it++) {
            const int idx = it * 256 + tid;
            const int r = idx >> 3, s8 = (idx & 7) * 8;
            cp_async16(Ks + r * PHK + s8,
                       Kh + ((size_t)b * SKV + n * KT + r) * INNER + h * DHEAD + s8);
            cp_async16(Vs + r * PHV + s8,
                       Vt + ((size_t)((b * HEADS + h) * DHEAD + r)) * SKV + n * KT + s8);
        }
        CP_COMMIT();
    };

    const int NT = SKV / KT;   // 32
    cp_tile(0, 0);
    cp_tile(1, 1);

    for (int n = 0; n < NT; n++) {
        const int buf = n % 3;

        if (n + 1 < NT) CP_WAIT1();   // oldest group (tile n) done
        else            CP_WAIT0();   // last tile: drain everything
        __syncthreads();

        if (n + 2 < NT) cp_tile(n + 2, (n + 2) % 3);

        const uint32_t* K32 = (const uint32_t*)(ash + buf * BUF_H);
        const uint32_t* V32 = (const uint32_t*)(ash + buf * BUF_H + KS_H);

        // ---- S[16x64] = Q @ K^T  (log2 domain)
        float s[8][4];
        #pragma unroll
        for (int j = 0; j < 8; j++)
            #pragma unroll
            for (int r = 0; r < 4; r++) s[j][r] = 0.f;

        #pragma unroll
        for (int ks = 0; ks < 4; ks++) {
            const int k8 = ks * 8;
            #pragma unroll
            for (int j = 0; j < 8; j++) {
                uint32_t bf[2];
                const int nn = j * 8 + g;
                bf[0] = K32[nn * (PHK / 2) + k8 + t];
                bf[1] = K32[nn * (PHK / 2) + k8 + t + 4];
                mma_f16(s[j], qa[ks], bf);
            }
        }

        // ---- warp-uniform max
        float tm = -INFINITY;
        #pragma unroll
        for (int j = 0; j < 8; j++)
            tm = fmaxf(tm, fmaxf(fmaxf(s[j][0], s[j][1]),
                                 fmaxf(s[j][2], s[j][3])));
        #pragma unroll
        for (int d = 16; d >= 1; d >>= 1)
            tm = fmaxf(tm, __shfl_xor_sync(0xffffffffu, tm, d));

        const float mn = fmaxf(m, tm);
        const float a  = ex2f(m - mn);
        if (a < 1.f) {
            ol[0] *= a; ol[1] *= a; ol[2] *= a; ol[3] *= a;
            #pragma unroll
            for (int j = 0; j < 8; j++) {
                o[j][0] *= a; o[j][1] *= a; o[j][2] *= a; o[j][3] *= a;
            }
        }
        m = mn;

        // ---- exp2 in-register
        #pragma unroll
        for (int j = 0; j < 8; j++) {
            s[j][0] = ex2f(s[j][0] - m);
            s[j][1] = ex2f(s[j][1] - m);
            s[j][2] = ex2f(s[j][2] - m);
            s[j][3] = ex2f(s[j][3] - m);
        }

        // ---- pack P; row sums via ones-MMA; O += P @ V
        const uint32_t onesbf[2] = { ONES2, ONES2 };
        #pragma unroll
        for (int ks = 0; ks < 4; ks++) {
            uint32_t pa[4];
            pa[0] = h2_u32(__floats2half2_rn(s[2 * ks    ][0], s[2 * ks    ][1]));
            pa[1] = h2_u32(__floats2half2_rn(s[2 * ks    ][2], s[2 * ks    ][3]));
            pa[2] = h2_u32(__floats2half2_rn(s[2 * ks + 1][0], s[2 * ks + 1][1]));
            pa[3] = h2_u32(__floats2half2_rn(s[2 * ks + 1][2], s[2 * ks + 1][3]));
            mma_f16(ol, pa, onesbf);   // l += P · 1
            const int k8 = ks * 8;
            #pragma unroll
            for (int j = 0; j < 8; j++) {
                uint32_t bf[2];
                const int nn = j * 8 + g;
                bf[0] = V32[nn * (PHV / 2) + k8 + t];
                bf[1] = V32[nn * (PHV / 2) + k8 + t + 4];
                mma_f16(o[j], pa, bf);
            }
        }
    }

    // ---- epilogue: fp16 O (l = ol[0] for row g, ol[2] for row g+8)
    const float inv0 = 1.f / ol[0];
    const float inv1 = 1.f / ol[2];
    __half* o0 = Oh + base;
    __half* o1 = o0 + 8 * INNER;
    #pragma unroll
    for (int j = 0; j < 8; j++) {
        const int c = j * 8 + 2 * t;
        *(half2*)(o0 + c) = __floats2half2_rn(o[j][0] * inv0, o[j][1] * inv0);
        *(half2*)(o1 + c) = __floats2half2_rn(o[j][2] * inv1, o[j][3] * inv1);
    }
}

// ===========================================================================
// kernel_launch
// ===========================================================================
extern "C" void kernel_launch(void* const* d_in, const int* in_sizes, int n_in,
                              void* d_out, int out_size)
{
    const float* x_q   = (const float*)d_in[0];
    const float* x_kv  = (const float*)d_in[1];
    const float* W_qkv = (const float*)d_in[2];  // [1024, 3072]
    const float* W_out = (const float*)d_in[3];  // [1024, 1024]
    const float* b_out = (const float*)d_in[4];  // [1024]
    float* out = (float*)d_out;

    __half *qh, *kh, *vh, *vt, *oh, *xqh, *xkvh, *wth, *woth;
    cudaGetSymbolAddress((void**)&qh,   g_qh);
    cudaGetSymbolAddress((void**)&kh,   g_kh);
    cudaGetSymbolAddress((void**)&vh,   g_vh);
    cudaGetSymbolAddress((void**)&vt,   g_vt);
    cudaGetSymbolAddress((void**)&oh,   g_oh);
    cudaGetSymbolAddress((void**)&xqh,  g_xqh);
    cudaGetSymbolAddress((void**)&xkvh, g_xkvh);
    cudaGetSymbolAddress((void**)&wth,  g_wth);
    cudaGetSymbolAddress((void**)&woth, g_woth);

    cudaFuncSetAttribute(gemm_qkv_h,
                         cudaFuncAttributeMaxDynamicSharedMemorySize, SM_BYTES);
    cudaFuncSetAttribute(gemm_out_h,
                         cudaFuncAttributeMaxDynamicSharedMemorySize, SM_BYTES);
    cudaFuncSetAttribute(attn_h,
                         cudaFuncAttributeMaxDynamicSharedMemorySize, ATT_SM_BYTES);

    // prep: fused fp16 conversions + fused weight transposes
    const int n4q = MQ * DIM / 4, n4kv = MKV * DIM / 4;
    f2h_all<<<(n4q + n4kv + 255) / 256, 256>>>(x_q, x_kv, xqh, xkvh, n4q, n4kv);
    transpose_f2h_all<<<dim3(128, 32), dim3(32, 8)>>>(W_qkv, W_out, wth, woth);

    // [Q*0.125*log2e | K | V] = [x_q | x_kv | x_kv] @ W_qkv  (fp16 out)
    gemm_qkv_h<<<dim3(24, MQ / 128), 256, SM_BYTES>>>(xqh, xkvh, wth, qh, kh, vh);

    // V -> V^T per (b,h)
    vt_prep<<<dim3(SKV / 64, HEADS, BATCH), 256>>>(vh, vt);

    // attention -> O fp16
    attn_h<<<dim3(SQ / 128, HEADS, BATCH), 256, ATT_SM_BYTES>>>(qh, kh, vt, oh);

    // out = O @ W_out + b_out  (fp32 out)
    gemm_out_h<<<dim3(DIM / 128, MQ / 128), 256, SM_BYTES>>>(oh, woth, out, b_out);
}